// round 14
// baseline (speedup 1.0000x reference)
#include <cuda_runtime.h>
#include <cuda_fp16.h>
#include <math.h>
#include <stdint.h>

// Problem constants
constexpr int Bc  = 2;
constexpr int Sc  = 4096;
constexpr int Dc  = 512;
constexpr int Hc  = 8;
constexpr int HDc = 64;
constexpr int FFc = 2048;
constexpr int BHc = Bc * Hc;        // 16
constexpr int Mc  = Bc * Sc;        // 8192

// Q pre-scale: 1/sqrt(64) * log2(e)  (so P = ex2(S') directly)
#define QSCALE 0.1803368801111204f

// ---------------------------------------------------------------------------
// Scratch (device globals)
// ---------------------------------------------------------------------------
__device__ float g_rs [BHc * Sc];
__device__ float g_y1 [Mc * Dc];
__device__ float g_att[Mc * Dc];
__device__ float g_y2 [Mc * Dc];

__device__ __half g_p  [(size_t)BHc * Sc * Sc];   // unnormalized P, fp16

__device__ __half g_xh [Mc * Dc];
__device__ __half g_qh [BHc * Sc * HDc];
__device__ __half g_kh [BHc * Sc * HDc];
__device__ __half g_ch [Mc * Dc];
__device__ __half g_ah [Mc * Dc];
__device__ __half g_zh [Mc * FFc];
__device__ __half g_wqh[Dc * Dc];
__device__ __half g_wkh[Dc * Dc];
__device__ __half g_wfh[Dc * Dc];
__device__ __half g_w1h[FFc * Dc];
__device__ __half g_w2h[Dc * FFc];

// ---------------------------------------------------------------------------
// Helpers
// ---------------------------------------------------------------------------
__device__ __forceinline__ uint32_t smem_u32(const void* p) {
    uint32_t a;
    asm("{ .reg .u64 t; cvta.to.shared.u64 t, %1; cvt.u32.u64 %0, t; }"
        : "=r"(a) : "l"(p));
    return a;
}
__device__ __forceinline__ void cp16(uint32_t saddr, const void* g) {
    asm volatile("cp.async.cg.shared.global [%0], [%1], 16;"
                 :: "r"(saddr), "l"(g) : "memory");
}
#define CP_COMMIT()  asm volatile("cp.async.commit_group;" ::: "memory")
#define CP_WAIT(n)   asm volatile("cp.async.wait_group %0;" :: "n"(n) : "memory")

__device__ __forceinline__ void ldsm_x4(uint32_t& r0, uint32_t& r1,
                                        uint32_t& r2, uint32_t& r3, uint32_t a) {
    asm volatile("ldmatrix.sync.aligned.m8n8.x4.shared.b16 {%0,%1,%2,%3}, [%4];"
                 : "=r"(r0), "=r"(r1), "=r"(r2), "=r"(r3) : "r"(a));
}
__device__ __forceinline__ void ldsm_x4_t(uint32_t& r0, uint32_t& r1,
                                          uint32_t& r2, uint32_t& r3, uint32_t a) {
    asm volatile("ldmatrix.sync.aligned.m8n8.x4.trans.shared.b16 {%0,%1,%2,%3}, [%4];"
                 : "=r"(r0), "=r"(r1), "=r"(r2), "=r"(r3) : "r"(a));
}

__device__ __forceinline__ void mma16816(float c[4],
        uint32_t a0, uint32_t a1, uint32_t a2, uint32_t a3,
        uint32_t b0, uint32_t b1) {
    asm volatile("mma.sync.aligned.m16n8k16.row.col.f32.f16.f16.f32 "
                 "{%0,%1,%2,%3}, {%4,%5,%6,%7}, {%8,%9}, {%0,%1,%2,%3};"
                 : "+f"(c[0]), "+f"(c[1]), "+f"(c[2]), "+f"(c[3])
                 : "r"(a0), "r"(a1), "r"(a2), "r"(a3), "r"(b0), "r"(b1));
}

// Single-instruction f32x2 -> f16x2 pack (y goes to high half)
__device__ __forceinline__ uint32_t pack_hf(float x, float y) {
    uint32_t r;
    asm("cvt.rn.f16x2.f32 %0, %1, %2;" : "=r"(r) : "f"(y), "f"(x));
    return r;
}
__device__ __forceinline__ float ex2f(float x) {
    float r;
    asm("ex2.approx.f32 %0, %1;" : "=f"(r) : "f"(x));
    return r;
}

// ---------------------------------------------------------------------------
// fp32 -> fp16 conversion
// ---------------------------------------------------------------------------
__global__ __launch_bounds__(256)
void cvt_hi(const float4* __restrict__ in, uint2* __restrict__ hi)
{
    size_t i = (size_t)blockIdx.x * 256 + threadIdx.x;
    float4 v = in[i];
    hi[i] = make_uint2(pack_hf(v.x, v.y), pack_hf(v.z, v.w));
}

// ---------------------------------------------------------------------------
// HMMA GEMM (fp16 x1), 3-stage cp.async.
// EPI 3: permuted fp16 store (K) ; 4: permuted fp16 store scaled (Q) ;
// EPI 1: fp32+residual ; 2: relu+fp16
// ---------------------------------------------------------------------------
constexpr int GP = 80;
constexpr int SM_A = 0, SM_W = 10240;
constexpr int GSTG = 20480;
constexpr int GEMM_SMEM3 = 3 * GSTG;           // 61440

template<int EPI>
__global__ __launch_bounds__(256, 2)
void gemm_mma(const __half* __restrict__ Ah,
              const __half* __restrict__ Wh,
              const float* __restrict__ res, float* __restrict__ Cf,
              __half* __restrict__ Ch,
              int N, int K)
{
    extern __shared__ __align__(16) char smd[];
    const uint32_t sb = smem_u32(smd);
    const int tid = threadIdx.x, lane = tid & 31, wid = tid >> 5;
    const int wm = wid >> 2, wn = wid & 3;
    const int m0 = blockIdx.y * 128, n0 = blockIdx.x * 128;
    const int NK = K >> 5;

    float acc[4][4][4];
    #pragma unroll
    for (int i = 0; i < 4; ++i)
        #pragma unroll
        for (int j = 0; j < 4; ++j)
            #pragma unroll
            for (int q = 0; q < 4; ++q) acc[i][j][q] = 0.f;

    auto issue = [&](int it, int stg) {
        uint32_t base = sb + stg * GSTG;
        #pragma unroll
        for (int i = 0; i < 2; ++i) {
            int c = tid + i * 256, row = c >> 2, part = c & 3;
            int so = row * GP + part * 16;
            size_t ga = (size_t)(m0 + row) * K + it * 32 + part * 8;
            size_t gw = (size_t)(n0 + row) * K + it * 32 + part * 8;
            cp16(base + SM_A + so, Ah + ga);
            cp16(base + SM_W + so, Wh + gw);
        }
        CP_COMMIT();
    };

    issue(0, 0);
    issue(1, 1);

    for (int it = 0; it < NK; ++it) {
        const int stg = it % 3;
        if (it + 2 < NK) { CP_WAIT(1); } else { CP_WAIT(0); }
        __syncthreads();
        if (it + 2 < NK) issue(it + 2, (it + 2) % 3);
        const uint32_t base = sb + stg * GSTG;

        #pragma unroll
        for (int ks = 0; ks < 2; ++ks) {
            uint32_t wh[4][2];
            #pragma unroll
            for (int nfp = 0; nfp < 2; ++nfp) {
                int ro = (wn * 32 + nfp * 16 + (lane & 15)) * GP + ks * 32 + (lane >> 4) * 16;
                uint32_t r0, r1, r2, r3;
                ldsm_x4(r0, r1, r2, r3, base + SM_W + ro);
                wh[nfp*2][0] = r0; wh[nfp*2+1][0] = r1;
                wh[nfp*2][1] = r2; wh[nfp*2+1][1] = r3;
            }
            #pragma unroll
            for (int mf = 0; mf < 4; ++mf) {
                int ro = (wm * 64 + mf * 16 + (lane & 15)) * GP + ks * 32 + (lane >> 4) * 16;
                uint32_t a0, a1, a2, a3;
                ldsm_x4(a0, a1, a2, a3, base + SM_A + ro);
                #pragma unroll
                for (int nf = 0; nf < 4; ++nf)
                    mma16816(acc[mf][nf], a0, a1, a2, a3, wh[nf][0], wh[nf][1]);
            }
        }
    }

    // epilogue
    #pragma unroll
    for (int mf = 0; mf < 4; ++mf) {
        int r0 = m0 + wm * 64 + mf * 16 + (lane >> 2);
        #pragma unroll
        for (int nf = 0; nf < 4; ++nf) {
            int c = n0 + wn * 32 + nf * 8 + (lane & 3) * 2;
            float v0 = acc[mf][nf][0], v1 = acc[mf][nf][1];
            float v2 = acc[mf][nf][2], v3 = acc[mf][nf][3];
            if (EPI == 3 || EPI == 4) {
                if (EPI == 4) {
                    v0 *= QSCALE; v1 *= QSCALE; v2 *= QSCALE; v3 *= QSCALE;
                }
                int hh = c >> 6, d = c & 63;
                int b0 = r0 >> 12, s0 = r0 & 4095;
                size_t o = (((size_t)(b0 * Hc + hh)) * Sc + s0) * HDc + d;
                int r1 = r0 + 8;
                int b1 = r1 >> 12, s1 = r1 & 4095;
                size_t o2 = (((size_t)(b1 * Hc + hh)) * Sc + s1) * HDc + d;
                *(uint32_t*)(Ch + o)  = pack_hf(v0, v1);
                *(uint32_t*)(Ch + o2) = pack_hf(v2, v3);
            } else if (EPI == 1) {
                size_t o = (size_t)r0 * N + c;
                float2 rr = *(const float2*)(res + o);
                *(float2*)(Cf + o) = make_float2(v0 + rr.x, v1 + rr.y);
                o = (size_t)(r0 + 8) * N + c;
                rr = *(const float2*)(res + o);
                *(float2*)(Cf + o) = make_float2(v2 + rr.x, v3 + rr.y);
            } else {
                size_t o = (size_t)r0 * N + c;
                *(uint32_t*)(Ch + o) = pack_hf(fmaxf(v0, 0.f), fmaxf(v1, 0.f));
                o = (size_t)(r0 + 8) * N + c;
                *(uint32_t*)(Ch + o) = pack_hf(fmaxf(v2, 0.f), fmaxf(v3, 0.f));
            }
        }
    }
}

// ---------------------------------------------------------------------------
// HMMA attention (fp16 x1), 8 M-warps, register-fragment PV.
// Q pre-scaled by 0.125*log2e at projection -> P = ex2(S) (single MUFU).
// Chunked along q-blocks: kernel processes q-blocks [qb, qb+gridDim.x).
// ---------------------------------------------------------------------------
constexpr int AP    = 144;
constexpr int A_QH  = 0;                        // 128*144 = 18432
constexpr int A_K0  = 18432;                    // 3 stages x 9216 -> end 46080
constexpr int ATT_SMEM = 46080 + 16;

__global__ __launch_bounds__(256, 2)
void attn_mma(int qb)
{
    extern __shared__ __align__(16) char sm[];
    const uint32_t sb = smem_u32(sm);
    const int tid = threadIdx.x, lane = tid & 31, wid = tid >> 5;  // wid 0..7
    const int bh = blockIdx.y, q0 = (qb + blockIdx.x) * 128;
    constexpr int NKT = Sc / 64;

    const __half* Qh = g_qh + (size_t)bh * Sc * HDc;
    const __half* Kh = g_kh + (size_t)bh * Sc * HDc;

    auto issueK = [&](int kt, int stg) {
        uint32_t base = sb + A_K0 + stg * 9216;
        #pragma unroll
        for (int i = 0; i < 2; ++i) {
            int c = tid + i * 256, row = c >> 3, part = c & 7;
            cp16(base + row * AP + part * 16,
                 Kh + (size_t)(kt * 64 + row) * HDc + part * 8);
        }
        CP_COMMIT();
    };

    issueK(0, 0);
    issueK(1, 1);

    // Q tile 128x64 fp16 = 1024 16B-chunks
    #pragma unroll
    for (int i = 0; i < 4; ++i) {
        int c = tid + i * 256, row = c >> 3, part = c & 7;
        size_t g = (size_t)(q0 + row) * HDc + part * 8;
        *(uint4*)(sm + A_QH + row * AP + part * 16) = *(const uint4*)(Qh + g);
    }

    float ctx[8][4];
    #pragma unroll
    for (int j = 0; j < 8; ++j)
        #pragma unroll
        for (int q = 0; q < 4; ++q) ctx[j][q] = 0.f;
    float rs0 = 0.f, rs1 = 0.f;

    const int rl = wid * 16 + (lane >> 2);

    for (int kt = 0; kt < NKT; ++kt) {
        const int stg = kt % 3;
        if (kt + 2 < NKT) { CP_WAIT(1); } else { CP_WAIT(0); }
        __syncthreads();
        if (kt + 2 < NKT) issueK(kt + 2, (kt + 2) % 3);
        const uint32_t KB = sb + A_K0 + stg * 9216;

        // ---- S = qh*kh (Q pre-scaled) ----
        float s[8][4];
        #pragma unroll
        for (int j = 0; j < 8; ++j)
            #pragma unroll
            for (int q = 0; q < 4; ++q) s[j][q] = 0.f;

        #pragma unroll
        for (int ks = 0; ks < 4; ++ks) {
            uint32_t bhf[8][2];
            #pragma unroll
            for (int nfp = 0; nfp < 4; ++nfp) {
                int ro = (nfp * 16 + (lane & 15)) * AP + ks * 32 + (lane >> 4) * 16;
                uint32_t r0, r1, r2, r3;
                ldsm_x4(r0, r1, r2, r3, KB + ro);
                bhf[nfp*2][0] = r0; bhf[nfp*2+1][0] = r1;
                bhf[nfp*2][1] = r2; bhf[nfp*2+1][1] = r3;
            }
            int ro = (wid * 16 + (lane & 15)) * AP + ks * 32 + (lane >> 4) * 16;
            uint32_t a0, a1, a2, a3;
            ldsm_x4(a0, a1, a2, a3, sb + A_QH + ro);
            #pragma unroll
            for (int nf = 0; nf < 8; ++nf)
                mma16816(s[nf], a0, a1, a2, a3, bhf[nf][0], bhf[nf][1]);
        }

        // ---- P = ex2(S): 1 MUFU per value; single-instr packs ----
        uint32_t qp[8][2];
        #pragma unroll
        for (int nf = 0; nf < 8; ++nf) {
            int cl_ = nf * 8 + (lane & 3) * 2;
            float p0 = ex2f(s[nf][0]);
            float p1 = ex2f(s[nf][1]);
            float p2 = ex2f(s[nf][2]);
            float p3 = ex2f(s[nf][3]);
            rs0 += p0 + p1;
            rs1 += p2 + p3;
            uint32_t q01 = pack_hf(p0, p1);
            uint32_t q23 = pack_hf(p2, p3);
            size_t gr = ((size_t)bh * Sc + q0 + rl) * Sc + kt * 64 + cl_;
            *(uint32_t*)(g_p + gr) = q01;
            *(uint32_t*)(g_p + gr + (size_t)8 * Sc) = q23;
            qp[nf][0] = q01;
            qp[nf][1] = q23;
        }

        // ---- ctx += P V over all 64 keys (register A fragments) ----
        #pragma unroll
        for (int ks2 = 0; ks2 < 4; ++ks2) {
            uint32_t vh[8][2];
            #pragma unroll
            for (int nfp = 0; nfp < 4; ++nfp) {
                int ro = (ks2 * 16 + (lane & 15)) * AP + nfp * 32 + (lane >> 4) * 16;
                uint32_t r0, r1, r2, r3;
                ldsm_x4_t(r0, r1, r2, r3, KB + ro);
                vh[nfp*2][0] = r0; vh[nfp*2][1] = r1;
                vh[nfp*2+1][0] = r2; vh[nfp*2+1][1] = r3;
            }
            uint32_t a0 = qp[2*ks2][0],   a1 = qp[2*ks2][1];
            uint32_t a2 = qp[2*ks2+1][0], a3 = qp[2*ks2+1][1];
            #pragma unroll
            for (int nf = 0; nf < 8; ++nf)
                mma16816(ctx[nf], a0, a1, a2, a3, vh[nf][0], vh[nf][1]);
        }
    }

    // ---- rowsum reduce within quad ----
    rs0 += __shfl_xor_sync(0xffffffffu, rs0, 1);
    rs0 += __shfl_xor_sync(0xffffffffu, rs0, 2);
    rs1 += __shfl_xor_sync(0xffffffffu, rs1, 1);
    rs1 += __shfl_xor_sync(0xffffffffu, rs1, 2);

    if ((lane & 3) == 0) {
        g_rs[(size_t)bh * Sc + q0 + rl]     = rs0;
        g_rs[(size_t)bh * Sc + q0 + rl + 8] = rs1;
    }

    // ---- normalize and store ctx (fp16, head-merged layout) ----
    const int bb = bh >> 3, hh = bh & 7;
    float i0 = 1.f / rs0;
    float i1 = 1.f / rs1;
    #pragma unroll
    for (int nf = 0; nf < 8; ++nf) {
        int d = nf * 8 + (lane & 3) * 2;
        size_t o = ((size_t)bb * Sc + q0 + rl) * Dc + hh * HDc + d;
        *(uint32_t*)(g_ch + o) = pack_hf(ctx[nf][0] * i0, ctx[nf][1] * i0);
        o += (size_t)8 * Dc;
        *(uint32_t*)(g_ch + o) = pack_hf(ctx[nf][2] * i1, ctx[nf][3] * i1);
    }
}

// ---------------------------------------------------------------------------
// attn = fp16 P / rowsum, one q-row chunk (rows [ro, ro+1024) per bh)
// ---------------------------------------------------------------------------
__global__ __launch_bounds__(256)
void norm_attn(float* __restrict__ attn, int ro)
{
    size_t i = (size_t)blockIdx.x * 256 + threadIdx.x;   // uint2 index in chunk
    size_t rloc = (i * 4) >> 12;                         // bh*1024 + rr
    int bhc = (int)(rloc >> 10);
    int rr  = (int)(rloc & 1023);
    size_t grow = (size_t)bhc * Sc + ro + rr;
    int col = (int)((i * 4) & 4095);
    float inv = 1.0f / g_rs[grow];
    uint2 pv = *(const uint2*)(g_p + grow * Sc + col);
    __half2 a = *(__half2*)&pv.x;
    __half2 b = *(__half2*)&pv.y;
    float2 fa = __half22float2(a);
    float2 fb = __half22float2(b);
    float4 o;
    o.x = fa.x * inv; o.y = fa.y * inv;
    o.z = fb.x * inv; o.w = fb.y * inv;
    *(float4*)(attn + grow * Sc + col) = o;
}

// ---------------------------------------------------------------------------
// LayerNorm; optionally emits fp16 copy
// ---------------------------------------------------------------------------
template<bool SPLIT>
__global__ __launch_bounds__(128)
void ln_kernel(const float* __restrict__ X, const float* __restrict__ gw,
               const float* __restrict__ bw, float* __restrict__ Y,
               __half* __restrict__ Yh)
{
    const int row = blockIdx.x;
    const int tid = threadIdx.x;
    float4 v = ((const float4*)(X + (size_t)row * Dc))[tid];
    float s = (v.x + v.y) + (v.z + v.w);
    float q = (v.x*v.x + v.y*v.y) + (v.z*v.z + v.w*v.w);
    #pragma unroll
    for (int o = 16; o; o >>= 1) {
        s += __shfl_xor_sync(0xffffffffu, s, o);
        q += __shfl_xor_sync(0xffffffffu, q, o);
    }
    __shared__ float ss[4], sq[4];
    if ((tid & 31) == 0) { ss[tid >> 5] = s; sq[tid >> 5] = q; }
    __syncthreads();
    s = ss[0] + ss[1] + ss[2] + ss[3];
    q = sq[0] + sq[1] + sq[2] + sq[3];
    const float mu  = s * (1.0f / Dc);
    const float var = q * (1.0f / Dc) - mu * mu;
    const float inv = rsqrtf(var + 1e-5f);
    float4 g4 = ((const float4*)gw)[tid];
    float4 b4 = ((const float4*)bw)[tid];
    float4 o4;
    o4.x = (v.x - mu) * inv * g4.x + b4.x;
    o4.y = (v.y - mu) * inv * g4.y + b4.y;
    o4.z = (v.z - mu) * inv * g4.z + b4.z;
    o4.w = (v.w - mu) * inv * g4.w + b4.w;
    ((float4*)(Y + (size_t)row * Dc))[tid] = o4;
    if (SPLIT) {
        size_t o = (size_t)row * Dc + tid * 4;
        *(uint32_t*)(Yh + o)     = pack_hf(o4.x, o4.y);
        *(uint32_t*)(Yh + o + 2) = pack_hf(o4.z, o4.w);
    }
}

// ---------------------------------------------------------------------------
extern "C" void kernel_launch(void* const* d_in, const int* in_sizes, int n_in,
                              void* d_out, int out_size)
{
    const float* x    = (const float*)d_in[0];
    const float* Wq   = (const float*)d_in[2];
    const float* Wk   = (const float*)d_in[3];
    const float* Wfc  = (const float*)d_in[5];
    const float* Wff1 = (const float*)d_in[6];
    const float* Wff2 = (const float*)d_in[7];
    const float* g1   = (const float*)d_in[8];
    const float* b1   = (const float*)d_in[9];
    const float* g2   = (const float*)d_in[10];
    const float* b2   = (const float*)d_in[11];

    float* out_feed = (float*)d_out;
    float* out_attn = (float*)d_out + (size_t)Mc * Dc;

    float *pY1, *pAtt, *pY2;
    cudaGetSymbolAddress((void**)&pY1,  g_y1);
    cudaGetSymbolAddress((void**)&pAtt, g_att);
    cudaGetSymbolAddress((void**)&pY2,  g_y2);

    __half *xh,*qh,*kh,*ch,*ah,*zh;
    __half *wqh,*wkh,*wfh,*w1h,*w2h;
    cudaGetSymbolAddress((void**)&xh,  g_xh);
    cudaGetSymbolAddress((void**)&qh,  g_qh);
    cudaGetSymbolAddress((void**)&kh,  g_kh);
    cudaGetSymbolAddress((void**)&ch,  g_ch);
    cudaGetSymbolAddress((void**)&ah,  g_ah);
    cudaGetSymbolAddress((void**)&zh,  g_zh);
    cudaGetSymbolAddress((void**)&wqh, g_wqh);
    cudaGetSymbolAddress((void**)&wkh, g_wkh);
    cudaGetSymbolAddress((void**)&wfh, g_wfh);
    cudaGetSymbolAddress((void**)&w1h, g_w1h);
    cudaGetSymbolAddress((void**)&w2h, g_w2h);

    cudaFuncSetAttribute(attn_mma,
                         cudaFuncAttributeMaxDynamicSharedMemorySize, ATT_SMEM);
    cudaFuncSetAttribute(gemm_mma<1>,
                         cudaFuncAttributeMaxDynamicSharedMemorySize, GEMM_SMEM3);
    cudaFuncSetAttribute(gemm_mma<2>,
                         cudaFuncAttributeMaxDynamicSharedMemorySize, GEMM_SMEM3);
    cudaFuncSetAttribute(gemm_mma<3>,
                         cudaFuncAttributeMaxDynamicSharedMemorySize, GEMM_SMEM3);
    cudaFuncSetAttribute(gemm_mma<4>,
                         cudaFuncAttributeMaxDynamicSharedMemorySize, GEMM_SMEM3);

    // One-time side-stream resources
    static cudaStream_t s2 = nullptr;
    static cudaEvent_t  eFork = nullptr, eJoin = nullptr, eW = nullptr;
    static cudaEvent_t  eX = nullptr, eK = nullptr;
    static cudaEvent_t  eC[4] = {nullptr, nullptr, nullptr, nullptr};
    if (s2 == nullptr) {
        cudaStreamCreateWithFlags(&s2, cudaStreamNonBlocking);
        cudaEventCreateWithFlags(&eFork, cudaEventDisableTiming);
        cudaEventCreateWithFlags(&eJoin, cudaEventDisableTiming);
        cudaEventCreateWithFlags(&eW,    cudaEventDisableTiming);
        cudaEventCreateWithFlags(&eX,    cudaEventDisableTiming);
        cudaEventCreateWithFlags(&eK,    cudaEventDisableTiming);
        for (int c = 0; c < 4; ++c)
            cudaEventCreateWithFlags(&eC[c], cudaEventDisableTiming);
    }

    // 0. x -> fp16 on main; weights -> fp16 on side stream
    cudaEventRecord(eFork, 0);
    cudaStreamWaitEvent(s2, eFork, 0);
    cvt_hi<<<(unsigned)((size_t)Mc * Dc / 1024), 256>>>((const float4*)x, (uint2*)xh);
    cudaEventRecord(eX, 0);
    auto cvtW = [&](const float* w, __half* hi, size_t n) {
        cvt_hi<<<(unsigned)(n / 1024), 256, 0, s2>>>((const float4*)w, (uint2*)hi);
    };
    cvtW(Wq,   wqh, (size_t)Dc * Dc);
    cvtW(Wk,   wkh, (size_t)Dc * Dc);
    cvtW(Wfc,  wfh, (size_t)Dc * Dc);
    cvtW(Wff1, w1h, (size_t)FFc * Dc);
    cvtW(Wff2, w2h, (size_t)Dc * FFc);
    cudaEventRecord(eW, s2);
    cudaStreamWaitEvent(0, eW, 0);
    cudaStreamWaitEvent(s2, eX, 0);

    // 1. Q proj (scaled, EPI4) on main || K proj (EPI3) on s2
    gemm_mma<4><<<dim3(Dc/128, Mc/128), 256, GEMM_SMEM3>>>(xh, wqh, nullptr, nullptr, qh, Dc, Dc);
    gemm_mma<3><<<dim3(Dc/128, Mc/128), 256, GEMM_SMEM3, s2>>>(xh, wkh, nullptr, nullptr, kh, Dc, Dc);
    cudaEventRecord(eK, s2);
    cudaStreamWaitEvent(0, eK, 0);

    // 2. Attention in 4 q-chunks; fork matching norm_attn quarter after each.
    //    Norm quarters (DRAM-bound) hide under later attention chunks
    //    (compute-bound) instead of competing with the FFN GEMMs.
    for (int c = 0; c < 4; ++c) {
        attn_mma<<<dim3(8, BHc), 256, ATT_SMEM>>>(c * 8);
        cudaEventRecord(eC[c], 0);
        cudaStreamWaitEvent(s2, eC[c], 0);
        size_t n4 = (size_t)BHc * 1024 * Sc / 4;   // quarter of the attn matrix
        norm_attn<<<(unsigned)(n4 / 256), 256, 0, s2>>>(out_attn, c * 1024);
    }

    // 3. y1 = x + ctx@Wfc^T ; att = LN(y1) (+ fp16)
    gemm_mma<1><<<dim3(Dc/128, Mc/128), 256, GEMM_SMEM3>>>(ch, wfh, x, pY1, nullptr, Dc, Dc);
    ln_kernel<true><<<Mc, 128>>>(pY1, g1, b1, pAtt, ah);

    // 4. z = relu(att@Wff1^T) ; y2 = att + z@Wff2^T ; out = LN(y2)
    gemm_mma<2><<<dim3(FFc/128, Mc/128), 256, GEMM_SMEM3>>>(ah, w1h, nullptr, nullptr, zh, FFc, Dc);
    gemm_mma<1><<<dim3(Dc/128, Mc/128), 256, GEMM_SMEM3>>>(zh, w2h, pAtt, pY2, nullptr, Dc, FFc);
    ln_kernel<false><<<Mc, 128>>>(pY2, g2, b2, out_feed, nullptr);

    // Join: main stream waits for the last norm quarter
    cudaEventRecord(eJoin, s2);
    cudaStreamWaitEvent(0, eJoin, 0);
}

// round 15
// speedup vs baseline: 1.2687x; 1.2687x over previous
#include <cuda_runtime.h>
#include <cuda_fp16.h>
#include <math.h>
#include <stdint.h>

// Problem constants
constexpr int Bc  = 2;
constexpr int Sc  = 4096;
constexpr int Dc  = 512;
constexpr int Hc  = 8;
constexpr int HDc = 64;
constexpr int FFc = 2048;
constexpr int BHc = Bc * Hc;        // 16
constexpr int Mc  = Bc * Sc;        // 8192

// Q pre-scale: 1/sqrt(64) * log2(e)  (so P = ex2(S) directly)
#define QSCALE 0.1803368801111204f

// ---------------------------------------------------------------------------
// Scratch (device globals)
// ---------------------------------------------------------------------------
__device__ float g_rs [BHc * Sc];
__device__ float g_y1 [Mc * Dc];
__device__ float g_att[Mc * Dc];
__device__ float g_y2 [Mc * Dc];

__device__ __half g_p  [(size_t)BHc * Sc * Sc];   // unnormalized P, fp16

__device__ __half g_xh [Mc * Dc];
__device__ __half g_qh [BHc * Sc * HDc];
__device__ __half g_kh [BHc * Sc * HDc];
__device__ __half g_ch [Mc * Dc];
__device__ __half g_ah [Mc * Dc];
__device__ __half g_zh [Mc * FFc];
__device__ __half g_wqh[Dc * Dc];
__device__ __half g_wkh[Dc * Dc];
__device__ __half g_wfh[Dc * Dc];
__device__ __half g_w1h[FFc * Dc];
__device__ __half g_w2h[Dc * FFc];

// ---------------------------------------------------------------------------
// Helpers
// ---------------------------------------------------------------------------
__device__ __forceinline__ uint32_t smem_u32(const void* p) {
    uint32_t a;
    asm("{ .reg .u64 t; cvta.to.shared.u64 t, %1; cvt.u32.u64 %0, t; }"
        : "=r"(a) : "l"(p));
    return a;
}
__device__ __forceinline__ void cp16(uint32_t saddr, const void* g) {
    asm volatile("cp.async.cg.shared.global [%0], [%1], 16;"
                 :: "r"(saddr), "l"(g) : "memory");
}
#define CP_COMMIT()  asm volatile("cp.async.commit_group;" ::: "memory")
#define CP_WAIT(n)   asm volatile("cp.async.wait_group %0;" :: "n"(n) : "memory")

__device__ __forceinline__ void ldsm_x4(uint32_t& r0, uint32_t& r1,
                                        uint32_t& r2, uint32_t& r3, uint32_t a) {
    asm volatile("ldmatrix.sync.aligned.m8n8.x4.shared.b16 {%0,%1,%2,%3}, [%4];"
                 : "=r"(r0), "=r"(r1), "=r"(r2), "=r"(r3) : "r"(a));
}
__device__ __forceinline__ void ldsm_x4_t(uint32_t& r0, uint32_t& r1,
                                          uint32_t& r2, uint32_t& r3, uint32_t a) {
    asm volatile("ldmatrix.sync.aligned.m8n8.x4.trans.shared.b16 {%0,%1,%2,%3}, [%4];"
                 : "=r"(r0), "=r"(r1), "=r"(r2), "=r"(r3) : "r"(a));
}

__device__ __forceinline__ void mma16816(float c[4],
        uint32_t a0, uint32_t a1, uint32_t a2, uint32_t a3,
        uint32_t b0, uint32_t b1) {
    asm volatile("mma.sync.aligned.m16n8k16.row.col.f32.f16.f16.f32 "
                 "{%0,%1,%2,%3}, {%4,%5,%6,%7}, {%8,%9}, {%0,%1,%2,%3};"
                 : "+f"(c[0]), "+f"(c[1]), "+f"(c[2]), "+f"(c[3])
                 : "r"(a0), "r"(a1), "r"(a2), "r"(a3), "r"(b0), "r"(b1));
}

// Single-instruction f32x2 -> f16x2 pack (y goes to high half)
__device__ __forceinline__ uint32_t pack_hf(float x, float y) {
    uint32_t r;
    asm("cvt.rn.f16x2.f32 %0, %1, %2;" : "=r"(r) : "f"(y), "f"(x));
    return r;
}
__device__ __forceinline__ float ex2f(float x) {
    float r;
    asm("ex2.approx.f32 %0, %1;" : "=f"(r) : "f"(x));
    return r;
}

// ---------------------------------------------------------------------------
// fp32 -> fp16 conversion
// ---------------------------------------------------------------------------
__global__ __launch_bounds__(256)
void cvt_hi(const float4* __restrict__ in, uint2* __restrict__ hi)
{
    size_t i = (size_t)blockIdx.x * 256 + threadIdx.x;
    float4 v = in[i];
    hi[i] = make_uint2(pack_hf(v.x, v.y), pack_hf(v.z, v.w));
}

// ---------------------------------------------------------------------------
// HMMA GEMM (fp16 x1), 3-stage cp.async.
// EPI 3: permuted fp16 store (K) ; 4: permuted fp16 store scaled (Q) ;
// EPI 1: fp32+residual ; 2: relu+fp16
// ---------------------------------------------------------------------------
constexpr int GP = 80;
constexpr int SM_A = 0, SM_W = 10240;
constexpr int GSTG = 20480;
constexpr int GEMM_SMEM3 = 3 * GSTG;           // 61440

template<int EPI>
__global__ __launch_bounds__(256, 2)
void gemm_mma(const __half* __restrict__ Ah,
              const __half* __restrict__ Wh,
              const float* __restrict__ res, float* __restrict__ Cf,
              __half* __restrict__ Ch,
              int N, int K)
{
    extern __shared__ __align__(16) char smd[];
    const uint32_t sb = smem_u32(smd);
    const int tid = threadIdx.x, lane = tid & 31, wid = tid >> 5;
    const int wm = wid >> 2, wn = wid & 3;
    const int m0 = blockIdx.y * 128, n0 = blockIdx.x * 128;
    const int NK = K >> 5;

    float acc[4][4][4];
    #pragma unroll
    for (int i = 0; i < 4; ++i)
        #pragma unroll
        for (int j = 0; j < 4; ++j)
            #pragma unroll
            for (int q = 0; q < 4; ++q) acc[i][j][q] = 0.f;

    auto issue = [&](int it, int stg) {
        uint32_t base = sb + stg * GSTG;
        #pragma unroll
        for (int i = 0; i < 2; ++i) {
            int c = tid + i * 256, row = c >> 2, part = c & 3;
            int so = row * GP + part * 16;
            size_t ga = (size_t)(m0 + row) * K + it * 32 + part * 8;
            size_t gw = (size_t)(n0 + row) * K + it * 32 + part * 8;
            cp16(base + SM_A + so, Ah + ga);
            cp16(base + SM_W + so, Wh + gw);
        }
        CP_COMMIT();
    };

    issue(0, 0);
    issue(1, 1);

    for (int it = 0; it < NK; ++it) {
        const int stg = it % 3;
        if (it + 2 < NK) { CP_WAIT(1); } else { CP_WAIT(0); }
        __syncthreads();
        if (it + 2 < NK) issue(it + 2, (it + 2) % 3);
        const uint32_t base = sb + stg * GSTG;

        #pragma unroll
        for (int ks = 0; ks < 2; ++ks) {
            uint32_t wh[4][2];
            #pragma unroll
            for (int nfp = 0; nfp < 2; ++nfp) {
                int ro = (wn * 32 + nfp * 16 + (lane & 15)) * GP + ks * 32 + (lane >> 4) * 16;
                uint32_t r0, r1, r2, r3;
                ldsm_x4(r0, r1, r2, r3, base + SM_W + ro);
                wh[nfp*2][0] = r0; wh[nfp*2+1][0] = r1;
                wh[nfp*2][1] = r2; wh[nfp*2+1][1] = r3;
            }
            #pragma unroll
            for (int mf = 0; mf < 4; ++mf) {
                int ro = (wm * 64 + mf * 16 + (lane & 15)) * GP + ks * 32 + (lane >> 4) * 16;
                uint32_t a0, a1, a2, a3;
                ldsm_x4(a0, a1, a2, a3, base + SM_A + ro);
                #pragma unroll
                for (int nf = 0; nf < 4; ++nf)
                    mma16816(acc[mf][nf], a0, a1, a2, a3, wh[nf][0], wh[nf][1]);
            }
        }
    }

    // epilogue
    #pragma unroll
    for (int mf = 0; mf < 4; ++mf) {
        int r0 = m0 + wm * 64 + mf * 16 + (lane >> 2);
        #pragma unroll
        for (int nf = 0; nf < 4; ++nf) {
            int c = n0 + wn * 32 + nf * 8 + (lane & 3) * 2;
            float v0 = acc[mf][nf][0], v1 = acc[mf][nf][1];
            float v2 = acc[mf][nf][2], v3 = acc[mf][nf][3];
            if (EPI == 3 || EPI == 4) {
                if (EPI == 4) {
                    v0 *= QSCALE; v1 *= QSCALE; v2 *= QSCALE; v3 *= QSCALE;
                }
                int hh = c >> 6, d = c & 63;
                int b0 = r0 >> 12, s0 = r0 & 4095;
                size_t o = (((size_t)(b0 * Hc + hh)) * Sc + s0) * HDc + d;
                int r1 = r0 + 8;
                int b1 = r1 >> 12, s1 = r1 & 4095;
                size_t o2 = (((size_t)(b1 * Hc + hh)) * Sc + s1) * HDc + d;
                *(uint32_t*)(Ch + o)  = pack_hf(v0, v1);
                *(uint32_t*)(Ch + o2) = pack_hf(v2, v3);
            } else if (EPI == 1) {
                size_t o = (size_t)r0 * N + c;
                float2 rr = *(const float2*)(res + o);
                *(float2*)(Cf + o) = make_float2(v0 + rr.x, v1 + rr.y);
                o = (size_t)(r0 + 8) * N + c;
                rr = *(const float2*)(res + o);
                *(float2*)(Cf + o) = make_float2(v2 + rr.x, v3 + rr.y);
            } else {
                size_t o = (size_t)r0 * N + c;
                *(uint32_t*)(Ch + o) = pack_hf(fmaxf(v0, 0.f), fmaxf(v1, 0.f));
                o = (size_t)(r0 + 8) * N + c;
                *(uint32_t*)(Ch + o) = pack_hf(fmaxf(v2, 0.f), fmaxf(v3, 0.f));
            }
        }
    }
}

// ---------------------------------------------------------------------------
// HMMA attention (fp16 x1), 8 M-warps, register-fragment PV, single launch.
// Q pre-scaled by 0.125*log2e at projection -> P = ex2(S) (single MUFU).
// ---------------------------------------------------------------------------
constexpr int AP    = 144;
constexpr int A_QH  = 0;                        // 128*144 = 18432
constexpr int A_K0  = 18432;                    // 3 stages x 9216 -> end 46080
constexpr int ATT_SMEM = 46080 + 16;

__global__ __launch_bounds__(256, 2)
void attn_mma()
{
    extern __shared__ __align__(16) char sm[];
    const uint32_t sb = smem_u32(sm);
    const int tid = threadIdx.x, lane = tid & 31, wid = tid >> 5;  // wid 0..7
    const int bh = blockIdx.y, q0 = blockIdx.x * 128;
    constexpr int NKT = Sc / 64;

    const __half* Qh = g_qh + (size_t)bh * Sc * HDc;
    const __half* Kh = g_kh + (size_t)bh * Sc * HDc;

    auto issueK = [&](int kt, int stg) {
        uint32_t base = sb + A_K0 + stg * 9216;
        #pragma unroll
        for (int i = 0; i < 2; ++i) {
            int c = tid + i * 256, row = c >> 3, part = c & 7;
            cp16(base + row * AP + part * 16,
                 Kh + (size_t)(kt * 64 + row) * HDc + part * 8);
        }
        CP_COMMIT();
    };

    issueK(0, 0);
    issueK(1, 1);

    // Q tile 128x64 fp16 = 1024 16B-chunks
    #pragma unroll
    for (int i = 0; i < 4; ++i) {
        int c = tid + i * 256, row = c >> 3, part = c & 7;
        size_t g = (size_t)(q0 + row) * HDc + part * 8;
        *(uint4*)(sm + A_QH + row * AP + part * 16) = *(const uint4*)(Qh + g);
    }

    float ctx[8][4];
    #pragma unroll
    for (int j = 0; j < 8; ++j)
        #pragma unroll
        for (int q = 0; q < 4; ++q) ctx[j][q] = 0.f;
    float rs0 = 0.f, rs1 = 0.f;

    const int rl = wid * 16 + (lane >> 2);

    for (int kt = 0; kt < NKT; ++kt) {
        const int stg = kt % 3;
        if (kt + 2 < NKT) { CP_WAIT(1); } else { CP_WAIT(0); }
        __syncthreads();
        if (kt + 2 < NKT) issueK(kt + 2, (kt + 2) % 3);
        const uint32_t KB = sb + A_K0 + stg * 9216;

        // ---- S = qh*kh (Q pre-scaled) ----
        float s[8][4];
        #pragma unroll
        for (int j = 0; j < 8; ++j)
            #pragma unroll
            for (int q = 0; q < 4; ++q) s[j][q] = 0.f;

        #pragma unroll
        for (int ks = 0; ks < 4; ++ks) {
            uint32_t bhf[8][2];
            #pragma unroll
            for (int nfp = 0; nfp < 4; ++nfp) {
                int ro = (nfp * 16 + (lane & 15)) * AP + ks * 32 + (lane >> 4) * 16;
                uint32_t r0, r1, r2, r3;
                ldsm_x4(r0, r1, r2, r3, KB + ro);
                bhf[nfp*2][0] = r0; bhf[nfp*2+1][0] = r1;
                bhf[nfp*2][1] = r2; bhf[nfp*2+1][1] = r3;
            }
            int ro = (wid * 16 + (lane & 15)) * AP + ks * 32 + (lane >> 4) * 16;
            uint32_t a0, a1, a2, a3;
            ldsm_x4(a0, a1, a2, a3, sb + A_QH + ro);
            #pragma unroll
            for (int nf = 0; nf < 8; ++nf)
                mma16816(s[nf], a0, a1, a2, a3, bhf[nf][0], bhf[nf][1]);
        }

        // ---- P = ex2(S): 1 MUFU per value; single-instr packs ----
        uint32_t qp[8][2];
        #pragma unroll
        for (int nf = 0; nf < 8; ++nf) {
            int cl_ = nf * 8 + (lane & 3) * 2;
            float p0 = ex2f(s[nf][0]);
            float p1 = ex2f(s[nf][1]);
            float p2 = ex2f(s[nf][2]);
            float p3 = ex2f(s[nf][3]);
            rs0 += p0 + p1;
            rs1 += p2 + p3;
            uint32_t q01 = pack_hf(p0, p1);
            uint32_t q23 = pack_hf(p2, p3);
            size_t gr = ((size_t)bh * Sc + q0 + rl) * Sc + kt * 64 + cl_;
            *(uint32_t*)(g_p + gr) = q01;
            *(uint32_t*)(g_p + gr + (size_t)8 * Sc) = q23;
            qp[nf][0] = q01;
            qp[nf][1] = q23;
        }

        // ---- ctx += P V over all 64 keys (register A fragments) ----
        #pragma unroll
        for (int ks2 = 0; ks2 < 4; ++ks2) {
            uint32_t vh[8][2];
            #pragma unroll
            for (int nfp = 0; nfp < 4; ++nfp) {
                int ro = (ks2 * 16 + (lane & 15)) * AP + nfp * 32 + (lane >> 4) * 16;
                uint32_t r0, r1, r2, r3;
                ldsm_x4_t(r0, r1, r2, r3, KB + ro);
                vh[nfp*2][0] = r0; vh[nfp*2][1] = r1;
                vh[nfp*2+1][0] = r2; vh[nfp*2+1][1] = r3;
            }
            uint32_t a0 = qp[2*ks2][0],   a1 = qp[2*ks2][1];
            uint32_t a2 = qp[2*ks2+1][0], a3 = qp[2*ks2+1][1];
            #pragma unroll
            for (int nf = 0; nf < 8; ++nf)
                mma16816(ctx[nf], a0, a1, a2, a3, vh[nf][0], vh[nf][1]);
        }
    }

    // ---- rowsum reduce within quad ----
    rs0 += __shfl_xor_sync(0xffffffffu, rs0, 1);
    rs0 += __shfl_xor_sync(0xffffffffu, rs0, 2);
    rs1 += __shfl_xor_sync(0xffffffffu, rs1, 1);
    rs1 += __shfl_xor_sync(0xffffffffu, rs1, 2);

    if ((lane & 3) == 0) {
        g_rs[(size_t)bh * Sc + q0 + rl]     = rs0;
        g_rs[(size_t)bh * Sc + q0 + rl + 8] = rs1;
    }

    // ---- normalize and store ctx (fp16, head-merged layout) ----
    const int bb = bh >> 3, hh = bh & 7;
    float i0 = 1.f / rs0;
    float i1 = 1.f / rs1;
    #pragma unroll
    for (int nf = 0; nf < 8; ++nf) {
        int d = nf * 8 + (lane & 3) * 2;
        size_t o = ((size_t)bb * Sc + q0 + rl) * Dc + hh * HDc + d;
        *(uint32_t*)(g_ch + o) = pack_hf(ctx[nf][0] * i0, ctx[nf][1] * i0);
        o += (size_t)8 * Dc;
        *(uint32_t*)(g_ch + o) = pack_hf(ctx[nf][2] * i1, ctx[nf][3] * i1);
    }
}

// ---------------------------------------------------------------------------
// attn = fp16 P / rowsum (full matrix)
// ---------------------------------------------------------------------------
__global__ __launch_bounds__(256)
void norm_attn(float* __restrict__ attn)
{
    size_t i = (size_t)blockIdx.x * 256 + threadIdx.x;   // uint2 index (4 halves)
    size_t row = (i * 4) >> 12;
    float inv = 1.0f / g_rs[row];
    uint2 pv = ((const uint2*)g_p)[i];
    __half2 a = *(__half2*)&pv.x;
    __half2 b = *(__half2*)&pv.y;
    float2 fa = __half22float2(a);
    float2 fb = __half22float2(b);
    float4 o;
    o.x = fa.x * inv; o.y = fa.y * inv;
    o.z = fb.x * inv; o.w = fb.y * inv;
    ((float4*)attn)[i] = o;
}

// ---------------------------------------------------------------------------
// LayerNorm; optionally emits fp16 copy
// ---------------------------------------------------------------------------
template<bool SPLIT>
__global__ __launch_bounds__(128)
void ln_kernel(const float* __restrict__ X, const float* __restrict__ gw,
               const float* __restrict__ bw, float* __restrict__ Y,
               __half* __restrict__ Yh)
{
    const int row = blockIdx.x;
    const int tid = threadIdx.x;
    float4 v = ((const float4*)(X + (size_t)row * Dc))[tid];
    float s = (v.x + v.y) + (v.z + v.w);
    float q = (v.x*v.x + v.y*v.y) + (v.z*v.z + v.w*v.w);
    #pragma unroll
    for (int o = 16; o; o >>= 1) {
        s += __shfl_xor_sync(0xffffffffu, s, o);
        q += __shfl_xor_sync(0xffffffffu, q, o);
    }
    __shared__ float ss[4], sq[4];
    if ((tid & 31) == 0) { ss[tid >> 5] = s; sq[tid >> 5] = q; }
    __syncthreads();
    s = ss[0] + ss[1] + ss[2] + ss[3];
    q = sq[0] + sq[1] + sq[2] + sq[3];
    const float mu  = s * (1.0f / Dc);
    const float var = q * (1.0f / Dc) - mu * mu;
    const float inv = rsqrtf(var + 1e-5f);
    float4 g4 = ((const float4*)gw)[tid];
    float4 b4 = ((const float4*)bw)[tid];
    float4 o4;
    o4.x = (v.x - mu) * inv * g4.x + b4.x;
    o4.y = (v.y - mu) * inv * g4.y + b4.y;
    o4.z = (v.z - mu) * inv * g4.z + b4.z;
    o4.w = (v.w - mu) * inv * g4.w + b4.w;
    ((float4*)(Y + (size_t)row * Dc))[tid] = o4;
    if (SPLIT) {
        size_t o = (size_t)row * Dc + tid * 4;
        *(uint32_t*)(Yh + o)     = pack_hf(o4.x, o4.y);
        *(uint32_t*)(Yh + o + 2) = pack_hf(o4.z, o4.w);
    }
}

// ---------------------------------------------------------------------------
extern "C" void kernel_launch(void* const* d_in, const int* in_sizes, int n_in,
                              void* d_out, int out_size)
{
    const float* x    = (const float*)d_in[0];
    const float* Wq   = (const float*)d_in[2];
    const float* Wk   = (const float*)d_in[3];
    const float* Wfc  = (const float*)d_in[5];
    const float* Wff1 = (const float*)d_in[6];
    const float* Wff2 = (const float*)d_in[7];
    const float* g1   = (const float*)d_in[8];
    const float* b1   = (const float*)d_in[9];
    const float* g2   = (const float*)d_in[10];
    const float* b2   = (const float*)d_in[11];

    float* out_feed = (float*)d_out;
    float* out_attn = (float*)d_out + (size_t)Mc * Dc;

    float *pY1, *pAtt, *pY2;
    cudaGetSymbolAddress((void**)&pY1,  g_y1);
    cudaGetSymbolAddress((void**)&pAtt, g_att);
    cudaGetSymbolAddress((void**)&pY2,  g_y2);

    __half *xh,*qh,*kh,*ch,*ah,*zh;
    __half *wqh,*wkh,*wfh,*w1h,*w2h;
    cudaGetSymbolAddress((void**)&xh,  g_xh);
    cudaGetSymbolAddress((void**)&qh,  g_qh);
    cudaGetSymbolAddress((void**)&kh,  g_kh);
    cudaGetSymbolAddress((void**)&ch,  g_ch);
    cudaGetSymbolAddress((void**)&ah,  g_ah);
    cudaGetSymbolAddress((void**)&zh,  g_zh);
    cudaGetSymbolAddress((void**)&wqh, g_wqh);
    cudaGetSymbolAddress((void**)&wkh, g_wkh);
    cudaGetSymbolAddress((void**)&wfh, g_wfh);
    cudaGetSymbolAddress((void**)&w1h, g_w1h);
    cudaGetSymbolAddress((void**)&w2h, g_w2h);

    cudaFuncSetAttribute(attn_mma,
                         cudaFuncAttributeMaxDynamicSharedMemorySize, ATT_SMEM);
    cudaFuncSetAttribute(gemm_mma<1>,
                         cudaFuncAttributeMaxDynamicSharedMemorySize, GEMM_SMEM3);
    cudaFuncSetAttribute(gemm_mma<2>,
                         cudaFuncAttributeMaxDynamicSharedMemorySize, GEMM_SMEM3);
    cudaFuncSetAttribute(gemm_mma<3>,
                         cudaFuncAttributeMaxDynamicSharedMemorySize, GEMM_SMEM3);
    cudaFuncSetAttribute(gemm_mma<4>,
                         cudaFuncAttributeMaxDynamicSharedMemorySize, GEMM_SMEM3);

    // One-time side-stream resources
    static cudaStream_t s2 = nullptr;
    static cudaEvent_t  eFork = nullptr, eJoin = nullptr, eW = nullptr;
    static cudaEvent_t  eX = nullptr, eK = nullptr;
    if (s2 == nullptr) {
        cudaStreamCreateWithFlags(&s2, cudaStreamNonBlocking);
        cudaEventCreateWithFlags(&eFork, cudaEventDisableTiming);
        cudaEventCreateWithFlags(&eJoin, cudaEventDisableTiming);
        cudaEventCreateWithFlags(&eW,    cudaEventDisableTiming);
        cudaEventCreateWithFlags(&eX,    cudaEventDisableTiming);
        cudaEventCreateWithFlags(&eK,    cudaEventDisableTiming);
    }

    // 0. x -> fp16 on main; weights -> fp16 on side stream
    cudaEventRecord(eFork, 0);
    cudaStreamWaitEvent(s2, eFork, 0);
    cvt_hi<<<(unsigned)((size_t)Mc * Dc / 1024), 256>>>((const float4*)x, (uint2*)xh);
    cudaEventRecord(eX, 0);
    auto cvtW = [&](const float* w, __half* hi, size_t n) {
        cvt_hi<<<(unsigned)(n / 1024), 256, 0, s2>>>((const float4*)w, (uint2*)hi);
    };
    cvtW(Wq,   wqh, (size_t)Dc * Dc);
    cvtW(Wk,   wkh, (size_t)Dc * Dc);
    cvtW(Wfc,  wfh, (size_t)Dc * Dc);
    cvtW(Wff1, w1h, (size_t)FFc * Dc);
    cvtW(Wff2, w2h, (size_t)Dc * FFc);
    cudaEventRecord(eW, s2);
    cudaStreamWaitEvent(0, eW, 0);
    cudaStreamWaitEvent(s2, eX, 0);

    // 1. Q proj (scaled, EPI4) on main || K proj (EPI3) on s2
    gemm_mma<4><<<dim3(Dc/128, Mc/128), 256, GEMM_SMEM3>>>(xh, wqh, nullptr, nullptr, qh, Dc, Dc);
    gemm_mma<3><<<dim3(Dc/128, Mc/128), 256, GEMM_SMEM3, s2>>>(xh, wkh, nullptr, nullptr, kh, Dc, Dc);
    cudaEventRecord(eK, s2);
    cudaStreamWaitEvent(0, eK, 0);

    // 2. Attention (single 512-CTA launch: full machine occupancy)
    attn_mma<<<dim3(Sc/128, BHc), 256, ATT_SMEM>>>();

    // Fork: normalize attn (fp16 -> fp32) on side stream, concurrent with FFN
    cudaEventRecord(eFork, 0);
    cudaStreamWaitEvent(s2, eFork, 0);
    {
        size_t n4 = (size_t)BHc * Sc * Sc / 4;
        norm_attn<<<(unsigned)(n4 / 256), 256, 0, s2>>>(out_attn);
    }

    // 3. y1 = x + ctx@Wfc^T ; att = LN(y1) (+ fp16)
    gemm_mma<1><<<dim3(Dc/128, Mc/128), 256, GEMM_SMEM3>>>(ch, wfh, x, pY1, nullptr, Dc, Dc);
    ln_kernel<true><<<Mc, 128>>>(pY1, g1, b1, pAtt, ah);

    // 4. z = relu(att@Wff1^T) ; y2 = att + z@Wff2^T ; out = LN(y2)
    gemm_mma<2><<<dim3(FFc/128, Mc/128), 256, GEMM_SMEM3>>>(ah, w1h, nullptr, nullptr, zh, FFc, Dc);
    gemm_mma<1><<<dim3(Dc/128, Mc/128), 256, GEMM_SMEM3>>>(zh, w2h, pAtt, pY2, nullptr, Dc, FFc);
    ln_kernel<false><<<Mc, 128>>>(pY2, g2, b2, out_feed, nullptr);

    // Join: main stream waits for norm_attn
    cudaEventRecord(eJoin, s2);
    cudaStreamWaitEvent(0, eJoin, 0);
}

// round 16
// speedup vs baseline: 1.2697x; 1.0008x over previous
#include <cuda_runtime.h>
#include <cuda_fp16.h>
#include <math.h>
#include <stdint.h>

// Problem constants
constexpr int Bc  = 2;
constexpr int Sc  = 4096;
constexpr int Dc  = 512;
constexpr int Hc  = 8;
constexpr int HDc = 64;
constexpr int FFc = 2048;
constexpr int BHc = Bc * Hc;        // 16
constexpr int Mc  = Bc * Sc;        // 8192

// Q pre-scale: 1/sqrt(64) * log2(e)  (so P = ex2(S) directly)
#define QSCALE 0.1803368801111204f

// ---------------------------------------------------------------------------
// Scratch (device globals)
// ---------------------------------------------------------------------------
__device__ float g_rs [BHc * Sc];
__device__ float g_y1 [Mc * Dc];
__device__ float g_att[Mc * Dc];
__device__ float g_y2 [Mc * Dc];

__device__ __half g_p  [(size_t)BHc * Sc * Sc];   // unnormalized P, fp16

__device__ __half g_xh [Mc * Dc];
__device__ __half g_qh [BHc * Sc * HDc];
__device__ __half g_kh [BHc * Sc * HDc];
__device__ __half g_ch [Mc * Dc];
__device__ __half g_ah [Mc * Dc];
__device__ __half g_zh [Mc * FFc];
__device__ __half g_wqk[2 * Dc * Dc];             // [Wq ; Wk] concatenated
__device__ __half g_wfh[Dc * Dc];
__device__ __half g_w1h[FFc * Dc];
__device__ __half g_w2h[Dc * FFc];

// ---------------------------------------------------------------------------
// Helpers
// ---------------------------------------------------------------------------
__device__ __forceinline__ uint32_t smem_u32(const void* p) {
    uint32_t a;
    asm("{ .reg .u64 t; cvta.to.shared.u64 t, %1; cvt.u32.u64 %0, t; }"
        : "=r"(a) : "l"(p));
    return a;
}
__device__ __forceinline__ void cp16(uint32_t saddr, const void* g) {
    asm volatile("cp.async.cg.shared.global [%0], [%1], 16;"
                 :: "r"(saddr), "l"(g) : "memory");
}
#define CP_COMMIT()  asm volatile("cp.async.commit_group;" ::: "memory")
#define CP_WAIT(n)   asm volatile("cp.async.wait_group %0;" :: "n"(n) : "memory")

__device__ __forceinline__ void ldsm_x4(uint32_t& r0, uint32_t& r1,
                                        uint32_t& r2, uint32_t& r3, uint32_t a) {
    asm volatile("ldmatrix.sync.aligned.m8n8.x4.shared.b16 {%0,%1,%2,%3}, [%4];"
                 : "=r"(r0), "=r"(r1), "=r"(r2), "=r"(r3) : "r"(a));
}
__device__ __forceinline__ void ldsm_x4_t(uint32_t& r0, uint32_t& r1,
                                          uint32_t& r2, uint32_t& r3, uint32_t a) {
    asm volatile("ldmatrix.sync.aligned.m8n8.x4.trans.shared.b16 {%0,%1,%2,%3}, [%4];"
                 : "=r"(r0), "=r"(r1), "=r"(r2), "=r"(r3) : "r"(a));
}

__device__ __forceinline__ void mma16816(float c[4],
        uint32_t a0, uint32_t a1, uint32_t a2, uint32_t a3,
        uint32_t b0, uint32_t b1) {
    asm volatile("mma.sync.aligned.m16n8k16.row.col.f32.f16.f16.f32 "
                 "{%0,%1,%2,%3}, {%4,%5,%6,%7}, {%8,%9}, {%0,%1,%2,%3};"
                 : "+f"(c[0]), "+f"(c[1]), "+f"(c[2]), "+f"(c[3])
                 : "r"(a0), "r"(a1), "r"(a2), "r"(a3), "r"(b0), "r"(b1));
}

// Single-instruction f32x2 -> f16x2 pack (y goes to high half)
__device__ __forceinline__ uint32_t pack_hf(float x, float y) {
    uint32_t r;
    asm("cvt.rn.f16x2.f32 %0, %1, %2;" : "=r"(r) : "f"(y), "f"(x));
    return r;
}
__device__ __forceinline__ float ex2f(float x) {
    float r;
    asm("ex2.approx.f32 %0, %1;" : "=f"(r) : "f"(x));
    return r;
}

// ---------------------------------------------------------------------------
// fp32 -> fp16 conversion
// ---------------------------------------------------------------------------
__global__ __launch_bounds__(256)
void cvt_hi(const float4* __restrict__ in, uint2* __restrict__ hi)
{
    size_t i = (size_t)blockIdx.x * 256 + threadIdx.x;
    float4 v = in[i];
    hi[i] = make_uint2(pack_hf(v.x, v.y), pack_hf(v.z, v.w));
}

// ---------------------------------------------------------------------------
// HMMA GEMM (fp16 x1), 3-stage cp.async.
// EPI 5: fused QK store — cols <512 -> Q (scaled), cols >=512 -> K
// EPI 1: fp32+residual ; 2: relu+fp16
// ---------------------------------------------------------------------------
constexpr int GP = 80;
constexpr int SM_A = 0, SM_W = 10240;
constexpr int GSTG = 20480;
constexpr int GEMM_SMEM3 = 3 * GSTG;           // 61440

template<int EPI>
__global__ __launch_bounds__(256, 2)
void gemm_mma(const __half* __restrict__ Ah,
              const __half* __restrict__ Wh,
              const float* __restrict__ res, float* __restrict__ Cf,
              __half* __restrict__ Ch, __half* __restrict__ Ch2,
              int N, int K)
{
    extern __shared__ __align__(16) char smd[];
    const uint32_t sb = smem_u32(smd);
    const int tid = threadIdx.x, lane = tid & 31, wid = tid >> 5;
    const int wm = wid >> 2, wn = wid & 3;
    const int m0 = blockIdx.y * 128, n0 = blockIdx.x * 128;
    const int NK = K >> 5;

    float acc[4][4][4];
    #pragma unroll
    for (int i = 0; i < 4; ++i)
        #pragma unroll
        for (int j = 0; j < 4; ++j)
            #pragma unroll
            for (int q = 0; q < 4; ++q) acc[i][j][q] = 0.f;

    auto issue = [&](int it, int stg) {
        uint32_t base = sb + stg * GSTG;
        #pragma unroll
        for (int i = 0; i < 2; ++i) {
            int c = tid + i * 256, row = c >> 2, part = c & 3;
            int so = row * GP + part * 16;
            size_t ga = (size_t)(m0 + row) * K + it * 32 + part * 8;
            size_t gw = (size_t)(n0 + row) * K + it * 32 + part * 8;
            cp16(base + SM_A + so, Ah + ga);
            cp16(base + SM_W + so, Wh + gw);
        }
        CP_COMMIT();
    };

    issue(0, 0);
    issue(1, 1);

    for (int it = 0; it < NK; ++it) {
        const int stg = it % 3;
        if (it + 2 < NK) { CP_WAIT(1); } else { CP_WAIT(0); }
        __syncthreads();
        if (it + 2 < NK) issue(it + 2, (it + 2) % 3);
        const uint32_t base = sb + stg * GSTG;

        #pragma unroll
        for (int ks = 0; ks < 2; ++ks) {
            uint32_t wh[4][2];
            #pragma unroll
            for (int nfp = 0; nfp < 2; ++nfp) {
                int ro = (wn * 32 + nfp * 16 + (lane & 15)) * GP + ks * 32 + (lane >> 4) * 16;
                uint32_t r0, r1, r2, r3;
                ldsm_x4(r0, r1, r2, r3, base + SM_W + ro);
                wh[nfp*2][0] = r0; wh[nfp*2+1][0] = r1;
                wh[nfp*2][1] = r2; wh[nfp*2+1][1] = r3;
            }
            #pragma unroll
            for (int mf = 0; mf < 4; ++mf) {
                int ro = (wm * 64 + mf * 16 + (lane & 15)) * GP + ks * 32 + (lane >> 4) * 16;
                uint32_t a0, a1, a2, a3;
                ldsm_x4(a0, a1, a2, a3, base + SM_A + ro);
                #pragma unroll
                for (int nf = 0; nf < 4; ++nf)
                    mma16816(acc[mf][nf], a0, a1, a2, a3, wh[nf][0], wh[nf][1]);
            }
        }
    }

    // epilogue
    #pragma unroll
    for (int mf = 0; mf < 4; ++mf) {
        int r0 = m0 + wm * 64 + mf * 16 + (lane >> 2);
        #pragma unroll
        for (int nf = 0; nf < 4; ++nf) {
            int c = n0 + wn * 32 + nf * 8 + (lane & 3) * 2;
            float v0 = acc[mf][nf][0], v1 = acc[mf][nf][1];
            float v2 = acc[mf][nf][2], v3 = acc[mf][nf][3];
            if (EPI == 5) {
                // fused QK: cols <512 are Q (apply QSCALE), cols >=512 are K
                __half* dst = (c < 512) ? Ch : Ch2;
                int cc = c & 511;
                if (c < 512) {
                    v0 *= QSCALE; v1 *= QSCALE; v2 *= QSCALE; v3 *= QSCALE;
                }
                int hh = cc >> 6, d = cc & 63;
                int b0 = r0 >> 12, s0 = r0 & 4095;
                size_t o = (((size_t)(b0 * Hc + hh)) * Sc + s0) * HDc + d;
                int r1 = r0 + 8;
                int b1 = r1 >> 12, s1 = r1 & 4095;
                size_t o2 = (((size_t)(b1 * Hc + hh)) * Sc + s1) * HDc + d;
                *(uint32_t*)(dst + o)  = pack_hf(v0, v1);
                *(uint32_t*)(dst + o2) = pack_hf(v2, v3);
            } else if (EPI == 1) {
                size_t o = (size_t)r0 * N + c;
                float2 rr = *(const float2*)(res + o);
                *(float2*)(Cf + o) = make_float2(v0 + rr.x, v1 + rr.y);
                o = (size_t)(r0 + 8) * N + c;
                rr = *(const float2*)(res + o);
                *(float2*)(Cf + o) = make_float2(v2 + rr.x, v3 + rr.y);
            } else {
                size_t o = (size_t)r0 * N + c;
                *(uint32_t*)(Ch + o) = pack_hf(fmaxf(v0, 0.f), fmaxf(v1, 0.f));
                o = (size_t)(r0 + 8) * N + c;
                *(uint32_t*)(Ch + o) = pack_hf(fmaxf(v2, 0.f), fmaxf(v3, 0.f));
            }
        }
    }
}

// ---------------------------------------------------------------------------
// HMMA attention (fp16 x1), 8 M-warps, register-fragment PV, single launch.
// Q pre-scaled by 0.125*log2e at projection -> P = ex2(S) (single MUFU).
// ---------------------------------------------------------------------------
constexpr int AP    = 144;
constexpr int A_QH  = 0;                        // 128*144 = 18432
constexpr int A_K0  = 18432;                    // 3 stages x 9216 -> end 46080
constexpr int ATT_SMEM = 46080 + 16;

__global__ __launch_bounds__(256, 2)
void attn_mma()
{
    extern __shared__ __align__(16) char sm[];
    const uint32_t sb = smem_u32(sm);
    const int tid = threadIdx.x, lane = tid & 31, wid = tid >> 5;  // wid 0..7
    const int bh = blockIdx.y, q0 = blockIdx.x * 128;
    constexpr int NKT = Sc / 64;

    const __half* Qh = g_qh + (size_t)bh * Sc * HDc;
    const __half* Kh = g_kh + (size_t)bh * Sc * HDc;

    auto issueK = [&](int kt, int stg) {
        uint32_t base = sb + A_K0 + stg * 9216;
        #pragma unroll
        for (int i = 0; i < 2; ++i) {
            int c = tid + i * 256, row = c >> 3, part = c & 7;
            cp16(base + row * AP + part * 16,
                 Kh + (size_t)(kt * 64 + row) * HDc + part * 8);
        }
        CP_COMMIT();
    };

    issueK(0, 0);
    issueK(1, 1);

    // Q tile 128x64 fp16 = 1024 16B-chunks
    #pragma unroll
    for (int i = 0; i < 4; ++i) {
        int c = tid + i * 256, row = c >> 3, part = c & 7;
        size_t g = (size_t)(q0 + row) * HDc + part * 8;
        *(uint4*)(sm + A_QH + row * AP + part * 16) = *(const uint4*)(Qh + g);
    }

    float ctx[8][4];
    #pragma unroll
    for (int j = 0; j < 8; ++j)
        #pragma unroll
        for (int q = 0; q < 4; ++q) ctx[j][q] = 0.f;
    float rs0 = 0.f, rs1 = 0.f;

    const int rl = wid * 16 + (lane >> 2);

    for (int kt = 0; kt < NKT; ++kt) {
        const int stg = kt % 3;
        if (kt + 2 < NKT) { CP_WAIT(1); } else { CP_WAIT(0); }
        __syncthreads();
        if (kt + 2 < NKT) issueK(kt + 2, (kt + 2) % 3);
        const uint32_t KB = sb + A_K0 + stg * 9216;

        // ---- S = qh*kh (Q pre-scaled) ----
        float s[8][4];
        #pragma unroll
        for (int j = 0; j < 8; ++j)
            #pragma unroll
            for (int q = 0; q < 4; ++q) s[j][q] = 0.f;

        #pragma unroll
        for (int ks = 0; ks < 4; ++ks) {
            uint32_t bhf[8][2];
            #pragma unroll
            for (int nfp = 0; nfp < 4; ++nfp) {
                int ro = (nfp * 16 + (lane & 15)) * AP + ks * 32 + (lane >> 4) * 16;
                uint32_t r0, r1, r2, r3;
                ldsm_x4(r0, r1, r2, r3, KB + ro);
                bhf[nfp*2][0] = r0; bhf[nfp*2+1][0] = r1;
                bhf[nfp*2][1] = r2; bhf[nfp*2+1][1] = r3;
            }
            int ro = (wid * 16 + (lane & 15)) * AP + ks * 32 + (lane >> 4) * 16;
            uint32_t a0, a1, a2, a3;
            ldsm_x4(a0, a1, a2, a3, sb + A_QH + ro);
            #pragma unroll
            for (int nf = 0; nf < 8; ++nf)
                mma16816(s[nf], a0, a1, a2, a3, bhf[nf][0], bhf[nf][1]);
        }

        // ---- P = ex2(S): 1 MUFU per value; single-instr packs ----
        uint32_t qp[8][2];
        #pragma unroll
        for (int nf = 0; nf < 8; ++nf) {
            int cl_ = nf * 8 + (lane & 3) * 2;
            float p0 = ex2f(s[nf][0]);
            float p1 = ex2f(s[nf][1]);
            float p2 = ex2f(s[nf][2]);
            float p3 = ex2f(s[nf][3]);
            rs0 += p0 + p1;
            rs1 += p2 + p3;
            uint32_t q01 = pack_hf(p0, p1);
            uint32_t q23 = pack_hf(p2, p3);
            size_t gr = ((size_t)bh * Sc + q0 + rl) * Sc + kt * 64 + cl_;
            *(uint32_t*)(g_p + gr) = q01;
            *(uint32_t*)(g_p + gr + (size_t)8 * Sc) = q23;
            qp[nf][0] = q01;
            qp[nf][1] = q23;
        }

        // ---- ctx += P V over all 64 keys (register A fragments) ----
        #pragma unroll
        for (int ks2 = 0; ks2 < 4; ++ks2) {
            uint32_t vh[8][2];
            #pragma unroll
            for (int nfp = 0; nfp < 4; ++nfp) {
                int ro = (ks2 * 16 + (lane & 15)) * AP + nfp * 32 + (lane >> 4) * 16;
                uint32_t r0, r1, r2, r3;
                ldsm_x4_t(r0, r1, r2, r3, KB + ro);
                vh[nfp*2][0] = r0; vh[nfp*2][1] = r1;
                vh[nfp*2+1][0] = r2; vh[nfp*2+1][1] = r3;
            }
            uint32_t a0 = qp[2*ks2][0],   a1 = qp[2*ks2][1];
            uint32_t a2 = qp[2*ks2+1][0], a3 = qp[2*ks2+1][1];
            #pragma unroll
            for (int nf = 0; nf < 8; ++nf)
                mma16816(ctx[nf], a0, a1, a2, a3, vh[nf][0], vh[nf][1]);
        }
    }

    // ---- rowsum reduce within quad ----
    rs0 += __shfl_xor_sync(0xffffffffu, rs0, 1);
    rs0 += __shfl_xor_sync(0xffffffffu, rs0, 2);
    rs1 += __shfl_xor_sync(0xffffffffu, rs1, 1);
    rs1 += __shfl_xor_sync(0xffffffffu, rs1, 2);

    if ((lane & 3) == 0) {
        g_rs[(size_t)bh * Sc + q0 + rl]     = rs0;
        g_rs[(size_t)bh * Sc + q0 + rl + 8] = rs1;
    }

    // ---- normalize and store ctx (fp16, head-merged layout) ----
    const int bb = bh >> 3, hh = bh & 7;
    float i0 = 1.f / rs0;
    float i1 = 1.f / rs1;
    #pragma unroll
    for (int nf = 0; nf < 8; ++nf) {
        int d = nf * 8 + (lane & 3) * 2;
        size_t o = ((size_t)bb * Sc + q0 + rl) * Dc + hh * HDc + d;
        *(uint32_t*)(g_ch + o) = pack_hf(ctx[nf][0] * i0, ctx[nf][1] * i0);
        o += (size_t)8 * Dc;
        *(uint32_t*)(g_ch + o) = pack_hf(ctx[nf][2] * i1, ctx[nf][3] * i1);
    }
}

// ---------------------------------------------------------------------------
// attn = fp16 P / rowsum (full matrix)
// ---------------------------------------------------------------------------
__global__ __launch_bounds__(256)
void norm_attn(float* __restrict__ attn)
{
    size_t i = (size_t)blockIdx.x * 256 + threadIdx.x;   // uint2 index (4 halves)
    size_t row = (i * 4) >> 12;
    float inv = 1.0f / g_rs[row];
    uint2 pv = ((const uint2*)g_p)[i];
    __half2 a = *(__half2*)&pv.x;
    __half2 b = *(__half2*)&pv.y;
    float2 fa = __half22float2(a);
    float2 fb = __half22float2(b);
    float4 o;
    o.x = fa.x * inv; o.y = fa.y * inv;
    o.z = fb.x * inv; o.w = fb.y * inv;
    ((float4*)attn)[i] = o;
}

// ---------------------------------------------------------------------------
// LayerNorm; optionally emits fp16 copy
// ---------------------------------------------------------------------------
template<bool SPLIT>
__global__ __launch_bounds__(128)
void ln_kernel(const float* __restrict__ X, const float* __restrict__ gw,
               const float* __restrict__ bw, float* __restrict__ Y,
               __half* __restrict__ Yh)
{
    const int row = blockIdx.x;
    const int tid = threadIdx.x;
    float4 v = ((const float4*)(X + (size_t)row * Dc))[tid];
    float s = (v.x + v.y) + (v.z + v.w);
    float q = (v.x*v.x + v.y*v.y) + (v.z*v.z + v.w*v.w);
    #pragma unroll
    for (int o = 16; o; o >>= 1) {
        s += __shfl_xor_sync(0xffffffffu, s, o);
        q += __shfl_xor_sync(0xffffffffu, q, o);
    }
    __shared__ float ss[4], sq[4];
    if ((tid & 31) == 0) { ss[tid >> 5] = s; sq[tid >> 5] = q; }
    __syncthreads();
    s = ss[0] + ss[1] + ss[2] + ss[3];
    q = sq[0] + sq[1] + sq[2] + sq[3];
    const float mu  = s * (1.0f / Dc);
    const float var = q * (1.0f / Dc) - mu * mu;
    const float inv = rsqrtf(var + 1e-5f);
    float4 g4 = ((const float4*)gw)[tid];
    float4 b4 = ((const float4*)bw)[tid];
    float4 o4;
    o4.x = (v.x - mu) * inv * g4.x + b4.x;
    o4.y = (v.y - mu) * inv * g4.y + b4.y;
    o4.z = (v.z - mu) * inv * g4.z + b4.z;
    o4.w = (v.w - mu) * inv * g4.w + b4.w;
    ((float4*)(Y + (size_t)row * Dc))[tid] = o4;
    if (SPLIT) {
        size_t o = (size_t)row * Dc + tid * 4;
        *(uint32_t*)(Yh + o)     = pack_hf(o4.x, o4.y);
        *(uint32_t*)(Yh + o + 2) = pack_hf(o4.z, o4.w);
    }
}

// ---------------------------------------------------------------------------
extern "C" void kernel_launch(void* const* d_in, const int* in_sizes, int n_in,
                              void* d_out, int out_size)
{
    const float* x    = (const float*)d_in[0];
    const float* Wq   = (const float*)d_in[2];
    const float* Wk   = (const float*)d_in[3];
    const float* Wfc  = (const float*)d_in[5];
    const float* Wff1 = (const float*)d_in[6];
    const float* Wff2 = (const float*)d_in[7];
    const float* g1   = (const float*)d_in[8];
    const float* b1   = (const float*)d_in[9];
    const float* g2   = (const float*)d_in[10];
    const float* b2   = (const float*)d_in[11];

    float* out_feed = (float*)d_out;
    float* out_attn = (float*)d_out + (size_t)Mc * Dc;

    float *pY1, *pAtt, *pY2;
    cudaGetSymbolAddress((void**)&pY1,  g_y1);
    cudaGetSymbolAddress((void**)&pAtt, g_att);
    cudaGetSymbolAddress((void**)&pY2,  g_y2);

    __half *xh,*qh,*kh,*ch,*ah,*zh;
    __half *wqk,*wfh,*w1h,*w2h;
    cudaGetSymbolAddress((void**)&xh,  g_xh);
    cudaGetSymbolAddress((void**)&qh,  g_qh);
    cudaGetSymbolAddress((void**)&kh,  g_kh);
    cudaGetSymbolAddress((void**)&ch,  g_ch);
    cudaGetSymbolAddress((void**)&ah,  g_ah);
    cudaGetSymbolAddress((void**)&zh,  g_zh);
    cudaGetSymbolAddress((void**)&wqk, g_wqk);
    cudaGetSymbolAddress((void**)&wfh, g_wfh);
    cudaGetSymbolAddress((void**)&w1h, g_w1h);
    cudaGetSymbolAddress((void**)&w2h, g_w2h);

    cudaFuncSetAttribute(attn_mma,
                         cudaFuncAttributeMaxDynamicSharedMemorySize, ATT_SMEM);
    cudaFuncSetAttribute(gemm_mma<1>,
                         cudaFuncAttributeMaxDynamicSharedMemorySize, GEMM_SMEM3);
    cudaFuncSetAttribute(gemm_mma<2>,
                         cudaFuncAttributeMaxDynamicSharedMemorySize, GEMM_SMEM3);
    cudaFuncSetAttribute(gemm_mma<5>,
                         cudaFuncAttributeMaxDynamicSharedMemorySize, GEMM_SMEM3);

    // One-time side-stream resources
    static cudaStream_t s2 = nullptr;
    static cudaEvent_t  eFork = nullptr, eJoin = nullptr, eW = nullptr;
    if (s2 == nullptr) {
        cudaStreamCreateWithFlags(&s2, cudaStreamNonBlocking);
        cudaEventCreateWithFlags(&eFork, cudaEventDisableTiming);
        cudaEventCreateWithFlags(&eJoin, cudaEventDisableTiming);
        cudaEventCreateWithFlags(&eW,    cudaEventDisableTiming);
    }

    // 0. x -> fp16 on main; weights -> fp16 on side stream
    //    (Wq/Wk converted into the concatenated g_wqk buffer)
    cudaEventRecord(eFork, 0);
    cudaStreamWaitEvent(s2, eFork, 0);
    cvt_hi<<<(unsigned)((size_t)Mc * Dc / 1024), 256>>>((const float4*)x, (uint2*)xh);
    auto cvtW = [&](const float* w, __half* hi, size_t n) {
        cvt_hi<<<(unsigned)(n / 1024), 256, 0, s2>>>((const float4*)w, (uint2*)hi);
    };
    cvtW(Wq,   wqk,           (size_t)Dc * Dc);
    cvtW(Wk,   wqk + Dc * Dc, (size_t)Dc * Dc);
    cvtW(Wfc,  wfh, (size_t)Dc * Dc);
    cvtW(Wff1, w1h, (size_t)FFc * Dc);
    cvtW(Wff2, w2h, (size_t)Dc * FFc);
    cudaEventRecord(eW, s2);
    cudaStreamWaitEvent(0, eW, 0);

    // 1. Fused Q+K projection: one N=1024 GEMM (A loaded once, 512 CTAs)
    gemm_mma<5><<<dim3(2 * Dc / 128, Mc / 128), 256, GEMM_SMEM3>>>(
        xh, wqk, nullptr, nullptr, qh, kh, 2 * Dc, Dc);

    // 2. Attention (single 512-CTA launch)
    attn_mma<<<dim3(Sc/128, BHc), 256, ATT_SMEM>>>();

    // Fork: normalize attn (fp16 -> fp32) on side stream, concurrent with FFN
    cudaEventRecord(eFork, 0);
    cudaStreamWaitEvent(s2, eFork, 0);
    {
        size_t n4 = (size_t)BHc * Sc * Sc / 4;
        norm_attn<<<(unsigned)(n4 / 256), 256, 0, s2>>>(out_attn);
    }

    // 3. y1 = x + ctx@Wfc^T ; att = LN(y1) (+ fp16)
    gemm_mma<1><<<dim3(Dc/128, Mc/128), 256, GEMM_SMEM3>>>(ch, wfh, x, pY1, nullptr, nullptr, Dc, Dc);
    ln_kernel<true><<<Mc, 128>>>(pY1, g1, b1, pAtt, ah);

    // 4. z = relu(att@Wff1^T) ; y2 = att + z@Wff2^T ; out = LN(y2)
    gemm_mma<2><<<dim3(FFc/128, Mc/128), 256, GEMM_SMEM3>>>(ah, w1h, nullptr, nullptr, zh, nullptr, FFc, Dc);
    gemm_mma<1><<<dim3(Dc/128, Mc/128), 256, GEMM_SMEM3>>>(zh, w2h, pAtt, pY2, nullptr, nullptr, Dc, FFc);
    ln_kernel<false><<<Mc, 128>>>(pY2, g2, b2, out_feed, nullptr);

    // Join: main stream waits for norm_attn
    cudaEventRecord(eJoin, s2);
    cudaStreamWaitEvent(0, eJoin, 0);
}

// round 17
// speedup vs baseline: 1.2730x; 1.0026x over previous
#include <cuda_runtime.h>
#include <cuda_fp16.h>
#include <math.h>
#include <stdint.h>

// Problem constants
constexpr int Bc  = 2;
constexpr int Sc  = 4096;
constexpr int Dc  = 512;
constexpr int Hc  = 8;
constexpr int HDc = 64;
constexpr int FFc = 2048;
constexpr int BHc = Bc * Hc;        // 16
constexpr int Mc  = Bc * Sc;        // 8192

// Q pre-scale: 1/sqrt(64) * log2(e)  (so P = ex2(S) directly)
#define QSCALE 0.1803368801111204f

// ---------------------------------------------------------------------------
// Scratch (device globals)
// ---------------------------------------------------------------------------
__device__ float g_rs [BHc * Sc];
__device__ float g_y1 [Mc * Dc];
__device__ float g_att[Mc * Dc];
__device__ float g_y2 [Mc * Dc];

__device__ __half g_p  [(size_t)BHc * Sc * Sc];   // unnormalized P, fp16

__device__ __half g_xh [Mc * Dc];
__device__ __half g_qh [BHc * Sc * HDc];
__device__ __half g_kh [BHc * Sc * HDc];
__device__ __half g_ch [Mc * Dc];
__device__ __half g_ah [Mc * Dc];
__device__ __half g_zh [Mc * FFc];
__device__ __half g_wqk[2 * Dc * Dc];             // [Wq ; Wk] concatenated
__device__ __half g_wfh[Dc * Dc];
__device__ __half g_w1h[FFc * Dc];
__device__ __half g_w2h[Dc * FFc];

// ---------------------------------------------------------------------------
// Helpers
// ---------------------------------------------------------------------------
__device__ __forceinline__ uint32_t smem_u32(const void* p) {
    uint32_t a;
    asm("{ .reg .u64 t; cvta.to.shared.u64 t, %1; cvt.u32.u64 %0, t; }"
        : "=r"(a) : "l"(p));
    return a;
}
__device__ __forceinline__ void cp16(uint32_t saddr, const void* g) {
    asm volatile("cp.async.cg.shared.global [%0], [%1], 16;"
                 :: "r"(saddr), "l"(g) : "memory");
}
#define CP_COMMIT()  asm volatile("cp.async.commit_group;" ::: "memory")
#define CP_WAIT(n)   asm volatile("cp.async.wait_group %0;" :: "n"(n) : "memory")

__device__ __forceinline__ void ldsm_x4(uint32_t& r0, uint32_t& r1,
                                        uint32_t& r2, uint32_t& r3, uint32_t a) {
    asm volatile("ldmatrix.sync.aligned.m8n8.x4.shared.b16 {%0,%1,%2,%3}, [%4];"
                 : "=r"(r0), "=r"(r1), "=r"(r2), "=r"(r3) : "r"(a));
}
__device__ __forceinline__ void ldsm_x4_t(uint32_t& r0, uint32_t& r1,
                                          uint32_t& r2, uint32_t& r3, uint32_t a) {
    asm volatile("ldmatrix.sync.aligned.m8n8.x4.trans.shared.b16 {%0,%1,%2,%3}, [%4];"
                 : "=r"(r0), "=r"(r1), "=r"(r2), "=r"(r3) : "r"(a));
}

__device__ __forceinline__ void mma16816(float c[4],
        uint32_t a0, uint32_t a1, uint32_t a2, uint32_t a3,
        uint32_t b0, uint32_t b1) {
    asm volatile("mma.sync.aligned.m16n8k16.row.col.f32.f16.f16.f32 "
                 "{%0,%1,%2,%3}, {%4,%5,%6,%7}, {%8,%9}, {%0,%1,%2,%3};"
                 : "+f"(c[0]), "+f"(c[1]), "+f"(c[2]), "+f"(c[3])
                 : "r"(a0), "r"(a1), "r"(a2), "r"(a3), "r"(b0), "r"(b1));
}

// Single-instruction f32x2 -> f16x2 pack (y goes to high half)
__device__ __forceinline__ uint32_t pack_hf(float x, float y) {
    uint32_t r;
    asm("cvt.rn.f16x2.f32 %0, %1, %2;" : "=r"(r) : "f"(y), "f"(x));
    return r;
}
__device__ __forceinline__ float ex2f(float x) {
    float r;
    asm("ex2.approx.f32 %0, %1;" : "=f"(r) : "f"(x));
    return r;
}

// ---------------------------------------------------------------------------
// fp32 -> fp16 conversion
// ---------------------------------------------------------------------------
__global__ __launch_bounds__(256)
void cvt_hi(const float4* __restrict__ in, uint2* __restrict__ hi)
{
    size_t i = (size_t)blockIdx.x * 256 + threadIdx.x;
    float4 v = in[i];
    hi[i] = make_uint2(pack_hf(v.x, v.y), pack_hf(v.z, v.w));
}

// ---------------------------------------------------------------------------
// HMMA GEMM (fp16 x1), 3-stage cp.async.
// EPI 5: fused QK store — cols <512 -> Q (scaled), cols >=512 -> K
// EPI 1: fp32+residual ; 2: relu+fp16
// ---------------------------------------------------------------------------
constexpr int GP = 80;
constexpr int SM_A = 0, SM_W = 10240;
constexpr int GSTG = 20480;
constexpr int GEMM_SMEM3 = 3 * GSTG;           // 61440

template<int EPI>
__global__ __launch_bounds__(256, 2)
void gemm_mma(const __half* __restrict__ Ah,
              const __half* __restrict__ Wh,
              const float* __restrict__ res, float* __restrict__ Cf,
              __half* __restrict__ Ch, __half* __restrict__ Ch2,
              int N, int K)
{
    extern __shared__ __align__(16) char smd[];
    const uint32_t sb = smem_u32(smd);
    const int tid = threadIdx.x, lane = tid & 31, wid = tid >> 5;
    const int wm = wid >> 2, wn = wid & 3;
    const int m0 = blockIdx.y * 128, n0 = blockIdx.x * 128;
    const int NK = K >> 5;

    float acc[4][4][4];
    #pragma unroll
    for (int i = 0; i < 4; ++i)
        #pragma unroll
        for (int j = 0; j < 4; ++j)
            #pragma unroll
            for (int q = 0; q < 4; ++q) acc[i][j][q] = 0.f;

    auto issue = [&](int it, int stg) {
        uint32_t base = sb + stg * GSTG;
        #pragma unroll
        for (int i = 0; i < 2; ++i) {
            int c = tid + i * 256, row = c >> 2, part = c & 3;
            int so = row * GP + part * 16;
            size_t ga = (size_t)(m0 + row) * K + it * 32 + part * 8;
            size_t gw = (size_t)(n0 + row) * K + it * 32 + part * 8;
            cp16(base + SM_A + so, Ah + ga);
            cp16(base + SM_W + so, Wh + gw);
        }
        CP_COMMIT();
    };

    issue(0, 0);
    issue(1, 1);

    for (int it = 0; it < NK; ++it) {
        const int stg = it % 3;
        if (it + 2 < NK) { CP_WAIT(1); } else { CP_WAIT(0); }
        __syncthreads();
        if (it + 2 < NK) issue(it + 2, (it + 2) % 3);
        const uint32_t base = sb + stg * GSTG;

        #pragma unroll
        for (int ks = 0; ks < 2; ++ks) {
            uint32_t wh[4][2];
            #pragma unroll
            for (int nfp = 0; nfp < 2; ++nfp) {
                int ro = (wn * 32 + nfp * 16 + (lane & 15)) * GP + ks * 32 + (lane >> 4) * 16;
                uint32_t r0, r1, r2, r3;
                ldsm_x4(r0, r1, r2, r3, base + SM_W + ro);
                wh[nfp*2][0] = r0; wh[nfp*2+1][0] = r1;
                wh[nfp*2][1] = r2; wh[nfp*2+1][1] = r3;
            }
            #pragma unroll
            for (int mf = 0; mf < 4; ++mf) {
                int ro = (wm * 64 + mf * 16 + (lane & 15)) * GP + ks * 32 + (lane >> 4) * 16;
                uint32_t a0, a1, a2, a3;
                ldsm_x4(a0, a1, a2, a3, base + SM_A + ro);
                #pragma unroll
                for (int nf = 0; nf < 4; ++nf)
                    mma16816(acc[mf][nf], a0, a1, a2, a3, wh[nf][0], wh[nf][1]);
            }
        }
    }

    // epilogue
    #pragma unroll
    for (int mf = 0; mf < 4; ++mf) {
        int r0 = m0 + wm * 64 + mf * 16 + (lane >> 2);
        #pragma unroll
        for (int nf = 0; nf < 4; ++nf) {
            int c = n0 + wn * 32 + nf * 8 + (lane & 3) * 2;
            float v0 = acc[mf][nf][0], v1 = acc[mf][nf][1];
            float v2 = acc[mf][nf][2], v3 = acc[mf][nf][3];
            if (EPI == 5) {
                __half* dst = (c < 512) ? Ch : Ch2;
                int cc = c & 511;
                if (c < 512) {
                    v0 *= QSCALE; v1 *= QSCALE; v2 *= QSCALE; v3 *= QSCALE;
                }
                int hh = cc >> 6, d = cc & 63;
                int b0 = r0 >> 12, s0 = r0 & 4095;
                size_t o = (((size_t)(b0 * Hc + hh)) * Sc + s0) * HDc + d;
                int r1 = r0 + 8;
                int b1 = r1 >> 12, s1 = r1 & 4095;
                size_t o2 = (((size_t)(b1 * Hc + hh)) * Sc + s1) * HDc + d;
                *(uint32_t*)(dst + o)  = pack_hf(v0, v1);
                *(uint32_t*)(dst + o2) = pack_hf(v2, v3);
            } else if (EPI == 1) {
                size_t o = (size_t)r0 * N + c;
                float2 rr = *(const float2*)(res + o);
                *(float2*)(Cf + o) = make_float2(v0 + rr.x, v1 + rr.y);
                o = (size_t)(r0 + 8) * N + c;
                rr = *(const float2*)(res + o);
                *(float2*)(Cf + o) = make_float2(v2 + rr.x, v3 + rr.y);
            } else {
                size_t o = (size_t)r0 * N + c;
                *(uint32_t*)(Ch + o) = pack_hf(fmaxf(v0, 0.f), fmaxf(v1, 0.f));
                o = (size_t)(r0 + 8) * N + c;
                *(uint32_t*)(Ch + o) = pack_hf(fmaxf(v2, 0.f), fmaxf(v3, 0.f));
            }
        }
    }
}

// ---------------------------------------------------------------------------
// HMMA attention (fp16 x1), 8 M-warps, register-fragment PV.
// Q fragments hoisted to registers before the main loop (loop-invariant).
// ---------------------------------------------------------------------------
constexpr int AP    = 144;
constexpr int A_QH  = 0;                        // 128*144 = 18432
constexpr int A_K0  = 18432;                    // 3 stages x 9216 -> end 46080
constexpr int ATT_SMEM = 46080 + 16;

__global__ __launch_bounds__(256, 2)
void attn_mma()
{
    extern __shared__ __align__(16) char sm[];
    const uint32_t sb = smem_u32(sm);
    const int tid = threadIdx.x, lane = tid & 31, wid = tid >> 5;  // wid 0..7
    const int bh = blockIdx.y, q0 = blockIdx.x * 128;
    constexpr int NKT = Sc / 64;

    const __half* Qh = g_qh + (size_t)bh * Sc * HDc;
    const __half* Kh = g_kh + (size_t)bh * Sc * HDc;

    auto issueK = [&](int kt, int stg) {
        uint32_t base = sb + A_K0 + stg * 9216;
        #pragma unroll
        for (int i = 0; i < 2; ++i) {
            int c = tid + i * 256, row = c >> 3, part = c & 7;
            cp16(base + row * AP + part * 16,
                 Kh + (size_t)(kt * 64 + row) * HDc + part * 8);
        }
        CP_COMMIT();
    };

    issueK(0, 0);
    issueK(1, 1);

    // Q tile 128x64 fp16 = 1024 16B-chunks
    #pragma unroll
    for (int i = 0; i < 4; ++i) {
        int c = tid + i * 256, row = c >> 3, part = c & 7;
        size_t g = (size_t)(q0 + row) * HDc + part * 8;
        *(uint4*)(sm + A_QH + row * AP + part * 16) = *(const uint4*)(Qh + g);
    }
    __syncthreads();     // Q tile visible to all warps

    // Hoist loop-invariant Q fragments into registers (16 regs)
    uint32_t aq[4][4];
    #pragma unroll
    for (int ks = 0; ks < 4; ++ks) {
        int ro = (wid * 16 + (lane & 15)) * AP + ks * 32 + (lane >> 4) * 16;
        ldsm_x4(aq[ks][0], aq[ks][1], aq[ks][2], aq[ks][3], sb + A_QH + ro);
    }

    float ctx[8][4];
    #pragma unroll
    for (int j = 0; j < 8; ++j)
        #pragma unroll
        for (int q = 0; q < 4; ++q) ctx[j][q] = 0.f;
    float rs0 = 0.f, rs1 = 0.f;

    const int rl = wid * 16 + (lane >> 2);

    for (int kt = 0; kt < NKT; ++kt) {
        const int stg = kt % 3;
        if (kt + 2 < NKT) { CP_WAIT(1); } else { CP_WAIT(0); }
        __syncthreads();
        if (kt + 2 < NKT) issueK(kt + 2, (kt + 2) % 3);
        const uint32_t KB = sb + A_K0 + stg * 9216;

        // ---- S = qh*kh (Q pre-scaled, fragments in registers) ----
        float s[8][4];
        #pragma unroll
        for (int j = 0; j < 8; ++j)
            #pragma unroll
            for (int q = 0; q < 4; ++q) s[j][q] = 0.f;

        #pragma unroll
        for (int ks = 0; ks < 4; ++ks) {
            uint32_t bhf[8][2];
            #pragma unroll
            for (int nfp = 0; nfp < 4; ++nfp) {
                int ro = (nfp * 16 + (lane & 15)) * AP + ks * 32 + (lane >> 4) * 16;
                uint32_t r0, r1, r2, r3;
                ldsm_x4(r0, r1, r2, r3, KB + ro);
                bhf[nfp*2][0] = r0; bhf[nfp*2+1][0] = r1;
                bhf[nfp*2][1] = r2; bhf[nfp*2+1][1] = r3;
            }
            #pragma unroll
            for (int nf = 0; nf < 8; ++nf)
                mma16816(s[nf], aq[ks][0], aq[ks][1], aq[ks][2], aq[ks][3],
                         bhf[nf][0], bhf[nf][1]);
        }

        // ---- P = ex2(S): 1 MUFU per value; single-instr packs ----
        uint32_t qp[8][2];
        #pragma unroll
        for (int nf = 0; nf < 8; ++nf) {
            int cl_ = nf * 8 + (lane & 3) * 2;
            float p0 = ex2f(s[nf][0]);
            float p1 = ex2f(s[nf][1]);
            float p2 = ex2f(s[nf][2]);
            float p3 = ex2f(s[nf][3]);
            rs0 += p0 + p1;
            rs1 += p2 + p3;
            uint32_t q01 = pack_hf(p0, p1);
            uint32_t q23 = pack_hf(p2, p3);
            size_t gr = ((size_t)bh * Sc + q0 + rl) * Sc + kt * 64 + cl_;
            *(uint32_t*)(g_p + gr) = q01;
            *(uint32_t*)(g_p + gr + (size_t)8 * Sc) = q23;
            qp[nf][0] = q01;
            qp[nf][1] = q23;
        }

        // ---- ctx += P V over all 64 keys (register A fragments) ----
        #pragma unroll
        for (int ks2 = 0; ks2 < 4; ++ks2) {
            uint32_t vh[8][2];
            #pragma unroll
            for (int nfp = 0; nfp < 4; ++nfp) {
                int ro = (ks2 * 16 + (lane & 15)) * AP + nfp * 32 + (lane >> 4) * 16;
                uint32_t r0, r1, r2, r3;
                ldsm_x4_t(r0, r1, r2, r3, KB + ro);
                vh[nfp*2][0] = r0; vh[nfp*2][1] = r1;
                vh[nfp*2+1][0] = r2; vh[nfp*2+1][1] = r3;
            }
            uint32_t a0 = qp[2*ks2][0],   a1 = qp[2*ks2][1];
            uint32_t a2 = qp[2*ks2+1][0], a3 = qp[2*ks2+1][1];
            #pragma unroll
            for (int nf = 0; nf < 8; ++nf)
                mma16816(ctx[nf], a0, a1, a2, a3, vh[nf][0], vh[nf][1]);
        }
    }

    // ---- rowsum reduce within quad ----
    rs0 += __shfl_xor_sync(0xffffffffu, rs0, 1);
    rs0 += __shfl_xor_sync(0xffffffffu, rs0, 2);
    rs1 += __shfl_xor_sync(0xffffffffu, rs1, 1);
    rs1 += __shfl_xor_sync(0xffffffffu, rs1, 2);

    if ((lane & 3) == 0) {
        g_rs[(size_t)bh * Sc + q0 + rl]     = rs0;
        g_rs[(size_t)bh * Sc + q0 + rl + 8] = rs1;
    }

    // ---- normalize and store ctx (fp16, head-merged layout) ----
    const int bb = bh >> 3, hh = bh & 7;
    float i0 = 1.f / rs0;
    float i1 = 1.f / rs1;
    #pragma unroll
    for (int nf = 0; nf < 8; ++nf) {
        int d = nf * 8 + (lane & 3) * 2;
        size_t o = ((size_t)bb * Sc + q0 + rl) * Dc + hh * HDc + d;
        *(uint32_t*)(g_ch + o) = pack_hf(ctx[nf][0] * i0, ctx[nf][1] * i0);
        o += (size_t)8 * Dc;
        *(uint32_t*)(g_ch + o) = pack_hf(ctx[nf][2] * i1, ctx[nf][3] * i1);
    }
}

// ---------------------------------------------------------------------------
// attn = fp16 P / rowsum (full matrix)
// ---------------------------------------------------------------------------
__global__ __launch_bounds__(256)
void norm_attn(float* __restrict__ attn)
{
    size_t i = (size_t)blockIdx.x * 256 + threadIdx.x;
    size_t row = (i * 4) >> 12;
    float inv = 1.0f / g_rs[row];
    uint2 pv = ((const uint2*)g_p)[i];
    __half2 a = *(__half2*)&pv.x;
    __half2 b = *(__half2*)&pv.y;
    float2 fa = __half22float2(a);
    float2 fb = __half22float2(b);
    float4 o;
    o.x = fa.x * inv; o.y = fa.y * inv;
    o.z = fb.x * inv; o.w = fb.y * inv;
    ((float4*)attn)[i] = o;
}

// ---------------------------------------------------------------------------
// LayerNorm; optionally emits fp16 copy
// ---------------------------------------------------------------------------
template<bool SPLIT>
__global__ __launch_bounds__(128)
void ln_kernel(const float* __restrict__ X, const float* __restrict__ gw,
               const float* __restrict__ bw, float* __restrict__ Y,
               __half* __restrict__ Yh)
{
    const int row = blockIdx.x;
    const int tid = threadIdx.x;
    float4 v = ((const float4*)(X + (size_t)row * Dc))[tid];
    float s = (v.x + v.y) + (v.z + v.w);
    float q = (v.x*v.x + v.y*v.y) + (v.z*v.z + v.w*v.w);
    #pragma unroll
    for (int o = 16; o; o >>= 1) {
        s += __shfl_xor_sync(0xffffffffu, s, o);
        q += __shfl_xor_sync(0xffffffffu, q, o);
    }
    __shared__ float ss[4], sq[4];
    if ((tid & 31) == 0) { ss[tid >> 5] = s; sq[tid >> 5] = q; }
    __syncthreads();
    s = ss[0] + ss[1] + ss[2] + ss[3];
    q = sq[0] + sq[1] + sq[2] + sq[3];
    const float mu  = s * (1.0f / Dc);
    const float var = q * (1.0f / Dc) - mu * mu;
    const float inv = rsqrtf(var + 1e-5f);
    float4 g4 = ((const float4*)gw)[tid];
    float4 b4 = ((const float4*)bw)[tid];
    float4 o4;
    o4.x = (v.x - mu) * inv * g4.x + b4.x;
    o4.y = (v.y - mu) * inv * g4.y + b4.y;
    o4.z = (v.z - mu) * inv * g4.z + b4.z;
    o4.w = (v.w - mu) * inv * g4.w + b4.w;
    ((float4*)(Y + (size_t)row * Dc))[tid] = o4;
    if (SPLIT) {
        size_t o = (size_t)row * Dc + tid * 4;
        *(uint32_t*)(Yh + o)     = pack_hf(o4.x, o4.y);
        *(uint32_t*)(Yh + o + 2) = pack_hf(o4.z, o4.w);
    }
}

// ---------------------------------------------------------------------------
extern "C" void kernel_launch(void* const* d_in, const int* in_sizes, int n_in,
                              void* d_out, int out_size)
{
    const float* x    = (const float*)d_in[0];
    const float* Wq   = (const float*)d_in[2];
    const float* Wk   = (const float*)d_in[3];
    const float* Wfc  = (const float*)d_in[5];
    const float* Wff1 = (const float*)d_in[6];
    const float* Wff2 = (const float*)d_in[7];
    const float* g1   = (const float*)d_in[8];
    const float* b1   = (const float*)d_in[9];
    const float* g2   = (const float*)d_in[10];
    const float* b2   = (const float*)d_in[11];

    float* out_feed = (float*)d_out;
    float* out_attn = (float*)d_out + (size_t)Mc * Dc;

    float *pY1, *pAtt, *pY2;
    cudaGetSymbolAddress((void**)&pY1,  g_y1);
    cudaGetSymbolAddress((void**)&pAtt, g_att);
    cudaGetSymbolAddress((void**)&pY2,  g_y2);

    __half *xh,*qh,*kh,*ch,*ah,*zh;
    __half *wqk,*wfh,*w1h,*w2h;
    cudaGetSymbolAddress((void**)&xh,  g_xh);
    cudaGetSymbolAddress((void**)&qh,  g_qh);
    cudaGetSymbolAddress((void**)&kh,  g_kh);
    cudaGetSymbolAddress((void**)&ch,  g_ch);
    cudaGetSymbolAddress((void**)&ah,  g_ah);
    cudaGetSymbolAddress((void**)&zh,  g_zh);
    cudaGetSymbolAddress((void**)&wqk, g_wqk);
    cudaGetSymbolAddress((void**)&wfh, g_wfh);
    cudaGetSymbolAddress((void**)&w1h, g_w1h);
    cudaGetSymbolAddress((void**)&w2h, g_w2h);

    cudaFuncSetAttribute(attn_mma,
                         cudaFuncAttributeMaxDynamicSharedMemorySize, ATT_SMEM);
    cudaFuncSetAttribute(gemm_mma<1>,
                         cudaFuncAttributeMaxDynamicSharedMemorySize, GEMM_SMEM3);
    cudaFuncSetAttribute(gemm_mma<2>,
                         cudaFuncAttributeMaxDynamicSharedMemorySize, GEMM_SMEM3);
    cudaFuncSetAttribute(gemm_mma<5>,
                         cudaFuncAttributeMaxDynamicSharedMemorySize, GEMM_SMEM3);

    // One-time side-stream resources
    static cudaStream_t s2 = nullptr;
    static cudaEvent_t  eFork = nullptr, eJoin = nullptr, eW = nullptr;
    if (s2 == nullptr) {
        cudaStreamCreateWithFlags(&s2, cudaStreamNonBlocking);
        cudaEventCreateWithFlags(&eFork, cudaEventDisableTiming);
        cudaEventCreateWithFlags(&eJoin, cudaEventDisableTiming);
        cudaEventCreateWithFlags(&eW,    cudaEventDisableTiming);
    }

    // 0. x -> fp16 on main; weights -> fp16 on side stream
    cudaEventRecord(eFork, 0);
    cudaStreamWaitEvent(s2, eFork, 0);
    cvt_hi<<<(unsigned)((size_t)Mc * Dc / 1024), 256>>>((const float4*)x, (uint2*)xh);
    auto cvtW = [&](const float* w, __half* hi, size_t n) {
        cvt_hi<<<(unsigned)(n / 1024), 256, 0, s2>>>((const float4*)w, (uint2*)hi);
    };
    cvtW(Wq,   wqk,           (size_t)Dc * Dc);
    cvtW(Wk,   wqk + Dc * Dc, (size_t)Dc * Dc);
    cvtW(Wfc,  wfh, (size_t)Dc * Dc);
    cvtW(Wff1, w1h, (size_t)FFc * Dc);
    cvtW(Wff2, w2h, (size_t)Dc * FFc);
    cudaEventRecord(eW, s2);
    cudaStreamWaitEvent(0, eW, 0);

    // 1. Fused Q+K projection: one N=1024 GEMM
    gemm_mma<5><<<dim3(2 * Dc / 128, Mc / 128), 256, GEMM_SMEM3>>>(
        xh, wqk, nullptr, nullptr, qh, kh, 2 * Dc, Dc);

    // 2. Attention (single 512-CTA launch)
    attn_mma<<<dim3(Sc/128, BHc), 256, ATT_SMEM>>>();

    // Fork: normalize attn (fp16 -> fp32) on side stream, concurrent with FFN
    cudaEventRecord(eFork, 0);
    cudaStreamWaitEvent(s2, eFork, 0);
    {
        size_t n4 = (size_t)BHc * Sc * Sc / 4;
        norm_attn<<<(unsigned)(n4 / 256), 256, 0, s2>>>(out_attn);
    }

    // 3. y1 = x + ctx@Wfc^T ; att = LN(y1) (+ fp16)
    gemm_mma<1><<<dim3(Dc/128, Mc/128), 256, GEMM_SMEM3>>>(ch, wfh, x, pY1, nullptr, nullptr, Dc, Dc);
    ln_kernel<true><<<Mc, 128>>>(pY1, g1, b1, pAtt, ah);

    // 4. z = relu(att@Wff1^T) ; y2 = att + z@Wff2^T ; out = LN(y2)
    gemm_mma<2><<<dim3(FFc/128, Mc/128), 256, GEMM_SMEM3>>>(ah, w1h, nullptr, nullptr, zh, nullptr, FFc, Dc);
    gemm_mma<1><<<dim3(Dc/128, Mc/128), 256, GEMM_SMEM3>>>(zh, w2h, pAtt, pY2, nullptr, nullptr, Dc, FFc);
    ln_kernel<false><<<Mc, 128>>>(pY2, g2, b2, out_feed, nullptr);

    // Join: main stream waits for norm_attn
    cudaEventRecord(eJoin, s2);
    cudaStreamWaitEvent(0, eJoin, 0);
}